// round 12
// baseline (speedup 1.0000x reference)
#include <cuda_runtime.h>
#include <cuda_fp16.h>
#include <cstdint>

namespace {
constexpr int kNodes = 50000;
constexpr int kEdges = 500000;
// np_kernel: sStrA 3*8K | sStrB 3*8K | sNf 4*8K | bn 512B | b1 4K
constexpr int NP_SMEM = 86528;
// fq_kernel: sQ 16*4K=64K | sEf 4*4K=16K | stream 2*16K=32K  => 114688
constexpr int FQ_SMEM = 114688;
}

// ============================================================================
// Static scratch. All half matrices K-PERMUTED per 16-group:
//   kperm(k) = (k&~15) + ((k&7)>>1)*4 + (k&1) + ((k>>3)&1)*2
// ============================================================================
__device__ __half g_pab[(size_t)kNodes * 1024];   // [node_f@W1a + b1 | node_f@W1b]
__device__ __half g_xt[(size_t)kNodes * 128];
__device__ __half g_wnt[128 * 128];
__device__ __half g_wet[128 * 64];
__device__ __half g_w1ab[1024 * 128];
__device__ __half g_w1c[512 * 128];
__device__ __half g_w2t[256 * 512];
__device__ float  g_bias1024[1024];
__device__ int    g_src[kEdges];
__device__ int    g_dst[kEdges];
__device__ int    g_is64;

// ============================================================================
// Helpers
// ============================================================================
__device__ __forceinline__ void cp_async16(void* smem, const void* gmem) {
    uint32_t s;
    asm("{ .reg .u64 t; cvta.to.shared.u64 t, %1; cvt.u32.u64 %0, t; }" : "=r"(s) : "l"(smem));
    asm volatile("cp.async.cg.shared.global [%0], [%1], 16;\n" :: "r"(s), "l"(gmem));
}
// L1-caching variant for weight tiles shared across CTAs
__device__ __forceinline__ void cp_async16_ca(void* smem, const void* gmem) {
    uint32_t s;
    asm("{ .reg .u64 t; cvta.to.shared.u64 t, %1; cvt.u32.u64 %0, t; }" : "=r"(s) : "l"(smem));
    asm volatile("cp.async.ca.shared.global [%0], [%1], 16;\n" :: "r"(s), "l"(gmem));
}
__device__ __forceinline__ void cp_commit() { asm volatile("cp.async.commit_group;\n"); }
__device__ __forceinline__ void cp_wait0()  { asm volatile("cp.async.wait_group 0;\n" ::: "memory"); }
__device__ __forceinline__ void cp_wait1()  { asm volatile("cp.async.wait_group 1;\n" ::: "memory"); }

__device__ __forceinline__ void mma16816(float* cc, uint32_t a0, uint32_t a1,
                                         uint32_t a2, uint32_t a3,
                                         uint32_t b0, uint32_t b1) {
    asm volatile(
        "mma.sync.aligned.m16n8k16.row.col.f32.f16.f16.f32 "
        "{%0,%1,%2,%3}, {%4,%5,%6,%7}, {%8,%9}, {%0,%1,%2,%3};"
        : "+f"(cc[0]), "+f"(cc[1]), "+f"(cc[2]), "+f"(cc[3])
        : "r"(a0), "r"(a1), "r"(a2), "r"(a3), "r"(b0), "r"(b1));
}
__host__ __device__ __forceinline__ int kperm(int k) {
    return (k & ~15) + (((k & 7) >> 1) << 2) + (k & 1) + (((k >> 3) & 1) << 1);
}

// ============================================================================
// Index prep
// ============================================================================
__global__ void detect_idx_kernel(const void* idx) {
    const int t = threadIdx.x;            // 256 threads, 1 value each
    const long long v = ((const long long*)idx)[t];
    int bad = (v < 0) || (v >= kNodes);
    int cnt = __syncthreads_count(bad);
    if (t == 0) g_is64 = (cnt == 0);
}
__global__ void conv_idx_kernel(const void* idx) {
    int i = blockIdx.x * blockDim.x + threadIdx.x;
    if (i >= kEdges) return;
    int s, d;
    if (g_is64) {
        const long long* p = (const long long*)idx;
        s = (int)p[i]; d = (int)p[kEdges + i];
    } else {
        const int* p = (const int*)idx;
        s = p[i]; d = p[kEdges + i];
    }
    g_src[i] = s; g_dst[i] = d;
}

// All weight/activation preps in one launch (block-range dispatch).
//  [0,12500)      x -> g_xt (float2->half2, kperm pair-adjacent)
//  [12500,12564)  Wn -> g_wnt
//  [12564,12596)  We -> g_wet
//  [12596,13108)  W2 -> g_w2t
//  [13108,13620)  W1 rows 0..255 -> g_w1ab
//  [13620,13876)  W1 rows 256..383 -> g_w1c
//  [13876,13880)  b1 -> g_bias1024
__global__ void prep_kernel(const float* __restrict__ x,
                            const float* __restrict__ Wn, const float* __restrict__ We,
                            const float* __restrict__ W1, const float* __restrict__ W2,
                            const float* __restrict__ b1) {
    const int b = blockIdx.x;
    const int t = threadIdx.x;
    if (b < 12500) {
        int i2 = b * 256 + t;
        int row = i2 >> 6, kp = (i2 & 63) * 2;
        float2 v = *(const float2*)(x + (size_t)row * 128 + kp);
        __half2 h; h.x = __float2half_rn(v.x); h.y = __float2half_rn(v.y);
        *(__half2*)(g_xt + (size_t)row * 128 + kperm(kp)) = h;
    } else if (b < 12564) {
        int i = (b - 12500) * 256 + t;
        int k = i >> 7, n = i & 127;
        g_wnt[n * 128 + kperm(k)] = __float2half_rn(Wn[i]);
    } else if (b < 12596) {
        int i = (b - 12564) * 256 + t;
        int k = i >> 7, n = i & 127;
        g_wet[n * 64 + kperm(k)] = __float2half_rn(We[i]);
    } else if (b < 13108) {
        int i = (b - 12596) * 256 + t;
        int k = i >> 8, n = i & 255;
        g_w2t[(size_t)n * 512 + kperm(k)] = __float2half_rn(W2[i]);
    } else if (b < 13620) {
        int i = (b - 13108) * 256 + t;
        int n = i >> 7, k = i & 127;
        int srcRow = (n < 512) ? k : (128 + k);
        int srcCol = (n < 512) ? n : (n - 512);
        g_w1ab[(size_t)n * 128 + kperm(k)] = __float2half_rn(W1[(size_t)srcRow * 512 + srcCol]);
    } else if (b < 13876) {
        int i = (b - 13620) * 256 + t;
        int n = i >> 7, k = i & 127;
        g_w1c[(size_t)n * 128 + kperm(k)] = __float2half_rn(W1[(size_t)(256 + k) * 512 + n]);
    } else {
        int i = (b - 13876) * 256 + t;
        if (i < 1024) g_bias1024[i] = (i < 512) ? b1[i] : 0.f;
    }
}

// ============================================================================
// Fused node pipeline: per-CTA 128 nodes.
//  Phase A: node_f = relu(x@Wnt + bn) -> sNf (4 A-format tiles, never DRAM)
//  Phase B: Pab = node_f @ W1ab + [b1|0] over 8 N-blocks of 128 -> g_pab
// A-tile format (128 rows x 64B): addr = tile + row*64 + ((j^(row&3))<<4).
// ============================================================================
__global__ __launch_bounds__(256, 2)
void np_kernel(const float* __restrict__ bn_, int M)
{
    extern __shared__ char smc[];
    char*  sStrA = smc;                    // 3 x 8192
    char*  sStrB = smc + 24576;            // 3 x 8192
    char*  sNf   = smc + 49152;            // 4 x 8192
    float* sBn   = (float*)(smc + 81920);  // 128
    float* sB1   = (float*)(smc + 82432);  // 1024

    const int tid  = threadIdx.x;
    const int lane = tid & 31;
    const int warp = tid >> 5;
    const int r    = lane >> 2;
    const int c    = lane & 3;
    const int wm   = (warp >> 2) * 64;
    const int wnl  = (warp & 3) * 32;
    const int bm   = blockIdx.x * 128;

    if (tid < 128) sBn[tid] = __ldg(bn_ + tid);
    for (int i = tid; i < 1024; i += 256) sB1[i] = g_bias1024[i];
    __syncthreads();

    // ---------------- Phase A: node encoder into sNf ----------------
    {
        auto loadA = [&](int s) {
            char* dA = sStrA + (s % 3) * 8192;
            char* dB = sStrB + (s % 3) * 8192;
#pragma unroll
            for (int t = 0; t < 2; ++t) {
                int idx = tid + t * 256;
                int row = idx >> 2, j = idx & 3;
                cp_async16(dA + row * 64 + ((j ^ (row & 3)) << 4),
                           g_xt + (size_t)min(bm + row, M - 1) * 128 + s * 32 + j * 8);
            }
#pragma unroll
            for (int t = 0; t < 2; ++t) {
                int idx = tid + t * 256;
                int n = idx >> 2, j = idx & 3;
                cp_async16_ca(dB + n * 64 + ((j ^ (n & 3)) << 4),
                              g_wnt + n * 128 + s * 32 + j * 8);
            }
        };
        float cf[4][4][4] = {};
        loadA(0); cp_commit();
        loadA(1); cp_commit();
#pragma unroll
        for (int s = 0; s < 4; ++s) {
            if (s + 1 < 4) cp_wait1(); else cp_wait0();
            __syncthreads();
            if (s + 2 < 4) { loadA(s + 2); cp_commit(); }
            const char* fA = sStrA + (s % 3) * 8192;
            const char* fB = sStrB + (s % 3) * 8192;
#pragma unroll
            for (int g = 0; g < 2; ++g) {
                const int coff = (((g * 2 + (c >> 1)) ^ (r & 3)) << 4) + (c & 1) * 8;
                uint2 ua[4], ub_[4], ubv[4];
#pragma unroll
                for (int ma = 0; ma < 4; ++ma) {
                    const int row0 = wm + ma * 16 + r;
                    ua[ma]  = *(const uint2*)(fA + row0 * 64 + coff);
                    ub_[ma] = *(const uint2*)(fA + (row0 + 8) * 64 + coff);
                }
#pragma unroll
                for (int na = 0; na < 4; ++na)
                    ubv[na] = *(const uint2*)(fB + (wnl + na * 8 + r) * 64 + coff);
#pragma unroll
                for (int ma = 0; ma < 4; ++ma)
#pragma unroll
                    for (int na = 0; na < 4; ++na)
                        mma16816(cf[ma][na], ua[ma].x, ub_[ma].x, ua[ma].y, ub_[ma].y,
                                 ubv[na].x, ubv[na].y);
            }
        }
        __syncthreads();   // mainloop fully done before sNf writes

        // epilogue: relu(+bn) -> sNf A-format
#pragma unroll
        for (int ma = 0; ma < 4; ++ma) {
#pragma unroll
            for (int na = 0; na < 4; ++na) {
                const int nloc = wnl + na * 8 + 2 * c;
                const int pcol = (nloc & ~15) + 4 * c + 2 * ((nloc >> 3) & 1);
                const int stage = pcol >> 5;
                const int byte = (pcol & 31) * 2;
                const int j = byte >> 4;
                float b0 = sBn[nloc], b1v = sBn[nloc + 1];
#pragma unroll
                for (int h = 0; h < 2; ++h) {
                    const int row = wm + ma * 16 + r + h * 8;
                    __half2 hv;
                    hv.x = __float2half_rn(fmaxf(cf[ma][na][h * 2]     + b0,  0.f));
                    hv.y = __float2half_rn(fmaxf(cf[ma][na][h * 2 + 1] + b1v, 0.f));
                    *(__half2*)(sNf + stage * 8192 + row * 64 +
                                ((j ^ (row & 3)) << 4) + (byte & 15)) = hv;
                }
            }
        }
        __syncthreads();
    }

    // ---------------- Phase B: Pab over 8 N-blocks ----------------
    for (int nb = 0; nb < 8; ++nb) {
        auto cpB = [&](int s) {
            char* dB = sStrB + (s % 3) * 8192;
#pragma unroll
            for (int t = 0; t < 2; ++t) {
                int idx = tid + t * 256;
                int n = idx >> 2, j = idx & 3;
                cp_async16_ca(dB + n * 64 + ((j ^ (n & 3)) << 4),
                              g_w1ab + (size_t)(nb * 128 + n) * 128 + s * 32 + j * 8);
            }
        };
        float cf[4][4][4] = {};
        cpB(0); cp_commit();
        cpB(1); cp_commit();
#pragma unroll
        for (int s = 0; s < 4; ++s) {
            if (s + 1 < 4) cp_wait1(); else cp_wait0();
            __syncthreads();
            if (s + 2 < 4) { cpB(s + 2); cp_commit(); }
            const char* fA = sNf + s * 8192;
            const char* fB = sStrB + (s % 3) * 8192;
#pragma unroll
            for (int g = 0; g < 2; ++g) {
                const int coff = (((g * 2 + (c >> 1)) ^ (r & 3)) << 4) + (c & 1) * 8;
                uint2 ua[4], ub_[4], ubv[4];
#pragma unroll
                for (int ma = 0; ma < 4; ++ma) {
                    const int row0 = wm + ma * 16 + r;
                    ua[ma]  = *(const uint2*)(fA + row0 * 64 + coff);
                    ub_[ma] = *(const uint2*)(fA + (row0 + 8) * 64 + coff);
                }
#pragma unroll
                for (int na = 0; na < 4; ++na)
                    ubv[na] = *(const uint2*)(fB + (wnl + na * 8 + r) * 64 + coff);
#pragma unroll
                for (int ma = 0; ma < 4; ++ma)
#pragma unroll
                    for (int na = 0; na < 4; ++na)
                        mma16816(cf[ma][na], ua[ma].x, ub_[ma].x, ua[ma].y, ub_[ma].y,
                                 ubv[na].x, ubv[na].y);
            }
        }
        __syncthreads();   // all reads of sStrB done before next nb overwrites

        // epilogue: +[b1|0], no relu, to g_pab (N=1024, kperm cols)
#pragma unroll
        for (int ma = 0; ma < 4; ++ma) {
            const int row0 = bm + wm + ma * 16 + r;
            const int row1 = row0 + 8;
#pragma unroll
            for (int na = 0; na < 4; ++na) {
                const int nloc = wnl + na * 8 + 2 * c;
                const int pcol = nb * 128 + (nloc & ~15) + 4 * c + 2 * ((nloc >> 3) & 1);
                const float b0 = sB1[nb * 128 + nloc];
                const float b1v = sB1[nb * 128 + nloc + 1];
                if (row0 < M) {
                    __half2 h;
                    h.x = __float2half_rn(cf[ma][na][0] + b0);
                    h.y = __float2half_rn(cf[ma][na][1] + b1v);
                    *(__half2*)(g_pab + (size_t)row0 * 1024 + pcol) = h;
                }
                if (row1 < M) {
                    __half2 h;
                    h.x = __float2half_rn(cf[ma][na][2] + b0);
                    h.y = __float2half_rn(cf[ma][na][3] + b1v);
                    *(__half2*)(g_pab + (size_t)row1 * 1024 + pcol) = h;
                }
            }
        }
    }
}

// ============================================================================
// Fused edge kernel: per-CTA 64 edges, everything in smem.
//  P0: edge_f = relu(eattr@We+be)          -> sEf (4 stage-tiles, 16KB)
//  P1: Q = edge_f @ W1c                    -> sQ  (16 stage-tiles, 64KB)
//  P2: A = relu(Pa[src]+Pb[dst]+Q) in place; out = relu(A@W2+b2).W3 + b3
// Stage-tile layout (64 rows x 64B): addr = tile + row*64 + ((j^(row&3))<<4).
// Phase-2 Pa/Pb gather prefetch is SINGLE-depth (register budget: 128/thread).
// ============================================================================
__global__ __launch_bounds__(256, 2)
void fq_kernel(const float* __restrict__ eattr,
               const float* __restrict__ be, const float* __restrict__ b2,
               const float* __restrict__ W3, const float* __restrict__ b3,
               float* __restrict__ outv, int M)
{
    extern __shared__ char smc[];
    char* sQ  = smc;            // 16 x 4096
    char* sEf = smc + 65536;    // 4 x 4096
    char* sStr = smc + 81920;   // 32768 stream region

    const int tid  = threadIdx.x;
    const int lane = tid & 31;
    const int warp = tid >> 5;
    const int r    = lane >> 2;
    const int c    = lane & 3;
    const int bm   = blockIdx.x * 64;

    auto stsC = [&](char* tiles, int row, int nloc, float v0, float v1) {
        const int pcol = (nloc & ~15) + 4 * c + 2 * ((nloc >> 3) & 1);
        const int stage = pcol >> 5;
        const int byte = (pcol & 31) * 2;
        const int j = byte >> 4;
        __half2 h; h.x = __float2half_rn(v0); h.y = __float2half_rn(v1);
        *(__half2*)(tiles + stage * 4096 + row * 64 + ((j ^ (row & 3)) << 4) + (byte & 15)) = h;
    };

    // ================= Phase 0: edge encoder =================
    {
        char* sA0 = sStr;             // 2 x 4096
        char* sB0 = sStr + 8192;      // 2 x 8192
        float* sBe = (float*)(sStr + 24576);   // 128 f32

        if (tid < 128) sBe[tid] = __ldg(be + tid);
#pragma unroll
        for (int t = 0; t < 4; ++t) {
            int idx = tid + t * 256;
            int stage = idx >> 9, rem = idx & 511;
            int n = rem >> 2, j = rem & 3;
            cp_async16_ca(sB0 + stage * 8192 + n * 64 + ((j ^ (n & 3)) << 4),
                          g_wet + (size_t)n * 64 + stage * 32 + j * 8);
        }
        cp_commit();
        {
            const int row = tid >> 2, seg = tid & 3;
            const int e = min(bm + row, M - 1);
            const float* es = eattr + (size_t)e * 64 + seg * 16;
            float ff[16];
#pragma unroll
            for (int q4 = 0; q4 < 4; ++q4) {
                float4 v = __ldg((const float4*)(es + q4 * 4));
                ff[q4 * 4] = v.x; ff[q4 * 4 + 1] = v.y;
                ff[q4 * 4 + 2] = v.z; ff[q4 * 4 + 3] = v.w;
            }
            __half arr[16];
#pragma unroll
            for (int kk = 0; kk < 16; ++kk) {
                int p = (((kk & 7) >> 1) << 2) + (kk & 1) + (((kk >> 3) & 1) << 1);
                arr[p] = __float2half_rn(ff[kk]);
            }
            const int stage = seg >> 1, jb = (seg & 1) * 2;
            char* base = sA0 + stage * 4096 + row * 64;
            *(uint4*)(base + (((jb    ) ^ (row & 3)) << 4)) = *(uint4*)arr;
            *(uint4*)(base + (((jb + 1) ^ (row & 3)) << 4)) = *(uint4*)(arr + 8);
        }
        cp_wait0();
        __syncthreads();

        const int wm0 = (warp >> 2) * 32;
        const int wnl0 = (warp & 3) * 32;
        float cf0[2][4][4] = {};
#pragma unroll
        for (int s0 = 0; s0 < 2; ++s0) {
            const char* fA = sA0 + s0 * 4096;
            const char* fB = sB0 + s0 * 8192;
#pragma unroll
            for (int g = 0; g < 2; ++g) {
                const int coff = (((g * 2 + (c >> 1)) ^ (r & 3)) << 4) + (c & 1) * 8;
                uint2 ua[2], ub_[2], ubv[4];
#pragma unroll
                for (int ma = 0; ma < 2; ++ma) {
                    const int row0 = wm0 + ma * 16 + r;
                    ua[ma]  = *(const uint2*)(fA + row0 * 64 + coff);
                    ub_[ma] = *(const uint2*)(fA + (row0 + 8) * 64 + coff);
                }
#pragma unroll
                for (int na = 0; na < 4; ++na)
                    ubv[na] = *(const uint2*)(fB + (wnl0 + na * 8 + r) * 64 + coff);
#pragma unroll
                for (int ma = 0; ma < 2; ++ma)
#pragma unroll
                    for (int na = 0; na < 4; ++na)
                        mma16816(cf0[ma][na], ua[ma].x, ub_[ma].x, ua[ma].y, ub_[ma].y,
                                 ubv[na].x, ubv[na].y);
            }
        }
        __syncthreads();
#pragma unroll
        for (int ma = 0; ma < 2; ++ma) {
            const int row0 = wm0 + ma * 16 + r;
#pragma unroll
            for (int na = 0; na < 4; ++na) {
                const int nloc = wnl0 + na * 8 + 2 * c;
                float b0 = sBe[nloc], b1v = sBe[nloc + 1];
                stsC(sEf, row0,     nloc, fmaxf(cf0[ma][na][0] + b0, 0.f),
                                          fmaxf(cf0[ma][na][1] + b1v, 0.f));
                stsC(sEf, row0 + 8, nloc, fmaxf(cf0[ma][na][2] + b0, 0.f),
                                          fmaxf(cf0[ma][na][3] + b1v, 0.f));
            }
        }
        __syncthreads();
    }

    // ================= Phase 1: Q = edge_f @ W1c (2 passes of N=256) ========
    {
        const int wnl = warp * 32;
        auto cpB1 = [&](int np, int s) {
            char* dB = sStr + (s & 1) * 16384;
#pragma unroll
            for (int t = 0; t < 4; ++t) {
                int idx = tid + t * 256;
                int n = idx >> 2, j = idx & 3;
                cp_async16_ca(dB + n * 64 + ((j ^ (n & 3)) << 4),
                              g_w1c + (size_t)(np * 256 + n) * 128 + s * 32 + j * 8);
            }
        };
#pragma unroll
        for (int np = 0; np < 2; ++np) {
            float cf1[4][4][4] = {};
            cpB1(np, 0); cp_commit();
            cpB1(np, 1); cp_commit();
#pragma unroll
            for (int s = 0; s < 4; ++s) {
                if (s + 1 < 4) cp_wait1(); else cp_wait0();
                __syncthreads();
                const char* fA = sEf + s * 4096;
                const char* fB = sStr + (s & 1) * 16384;
#pragma unroll
                for (int g = 0; g < 2; ++g) {
                    const int coff = (((g * 2 + (c >> 1)) ^ (r & 3)) << 4) + (c & 1) * 8;
                    uint2 ua[4], ub_[4], ubv[4];
#pragma unroll
                    for (int ma = 0; ma < 4; ++ma) {
                        const int row0 = ma * 16 + r;
                        ua[ma]  = *(const uint2*)(fA + row0 * 64 + coff);
                        ub_[ma] = *(const uint2*)(fA + (row0 + 8) * 64 + coff);
                    }
#pragma unroll
                    for (int na = 0; na < 4; ++na)
                        ubv[na] = *(const uint2*)(fB + (wnl + na * 8 + r) * 64 + coff);
#pragma unroll
                    for (int ma = 0; ma < 4; ++ma)
#pragma unroll
                        for (int na = 0; na < 4; ++na)
                            mma16816(cf1[ma][na], ua[ma].x, ub_[ma].x, ua[ma].y, ub_[ma].y,
                                     ubv[na].x, ubv[na].y);
                }
                __syncthreads();
                if (s + 2 < 4) { cpB1(np, s + 2); cp_commit(); }
            }
#pragma unroll
            for (int ma = 0; ma < 4; ++ma) {
                const int row0 = ma * 16 + r;
#pragma unroll
                for (int na = 0; na < 4; ++na) {
                    const int nloc = np * 256 + wnl + na * 8 + 2 * c;
                    stsC(sQ, row0,     nloc, cf1[ma][na][0], cf1[ma][na][1]);
                    stsC(sQ, row0 + 8, nloc, cf1[ma][na][2], cf1[ma][na][3]);
                }
            }
            __syncthreads();
        }
    }

    // ================= Phase 2: W2 + W3 =================
    {
        float* sB2 = (float*)sEf;            // 256 f32
        float* sW3 = (float*)(sEf + 1024);   // 256 f32
        float* psum = (float*)(sEf + 2048);  // 64 x 8 f32
        sB2[tid] = __ldg(b2 + tid);
        sW3[tid] = __ldg(W3 + tid);

        const int row = tid >> 2, j = tid & 3;
        const int e = min(bm + row, M - 1);
        const __half* paP = g_pab + (size_t)g_src[e] * 1024;
        const __half* pbP = g_pab + (size_t)g_dst[e] * 1024 + 512;
        char* qaddrBase = sQ + row * 64 + ((j ^ (row & 3)) << 4);

        uint4 ra, rb;
        auto ldgA = [&](int s) {
            ra = __ldg((const uint4*)(paP + s * 32 + j * 8));
            rb = __ldg((const uint4*)(pbP + s * 32 + j * 8));
        };
        auto finA = [&](int s) {
            uint4 q4 = *(uint4*)(qaddrBase + s * 4096);
            const half2* qh = (const half2*)&q4;
            const half2* ha = (const half2*)&ra;
            const half2* hb = (const half2*)&rb;
            half2 v[4];
            const half2 z = __float2half2_rn(0.f);
#pragma unroll
            for (int i = 0; i < 4; ++i)
                v[i] = __hmax2(__hadd2(__hadd2(qh[i], ha[i]), hb[i]), z);
            *(uint4*)(qaddrBase + s * 4096) = *(uint4*)v;
        };
        auto cpB2 = [&](int s) {
            char* dB = sStr + (s & 1) * 16384;
#pragma unroll
            for (int t = 0; t < 4; ++t) {
                int idx = tid + t * 256;
                int n = idx >> 2, j2 = idx & 3;
                cp_async16_ca(dB + n * 64 + ((j2 ^ (n & 3)) << 4),
                              g_w2t + (size_t)n * 512 + s * 32 + j2 * 8);
            }
        };

        const int wnl = warp * 32;
        float cf[4][4][4] = {};

        ldgA(0);
        cpB2(0); cp_commit();
        cpB2(1); cp_commit();

#pragma unroll 1
        for (int s = 0; s < 16; ++s) {
            finA(s);
            if (s + 1 < 16) ldgA(s + 1);
            if (s + 1 < 16) cp_wait1(); else cp_wait0();
            __syncthreads();
            const char* fA = sQ + s * 4096;
            const char* fB = sStr + (s & 1) * 16384;
#pragma unroll
            for (int g = 0; g < 2; ++g) {
                const int coff = (((g * 2 + (c >> 1)) ^ (r & 3)) << 4) + (c & 1) * 8;
                uint2 ua[4], ub_[4], ubv[4];
#pragma unroll
                for (int ma = 0; ma < 4; ++ma) {
                    const int row0 = ma * 16 + r;
                    ua[ma]  = *(const uint2*)(fA + row0 * 64 + coff);
                    ub_[ma] = *(const uint2*)(fA + (row0 + 8) * 64 + coff);
                }
#pragma unroll
                for (int na = 0; na < 4; ++na)
                    ubv[na] = *(const uint2*)(fB + (wnl + na * 8 + r) * 64 + coff);
#pragma unroll
                for (int ma = 0; ma < 4; ++ma)
#pragma unroll
                    for (int na = 0; na < 4; ++na)
                        mma16816(cf[ma][na], ua[ma].x, ub_[ma].x, ua[ma].y, ub_[ma].y,
                                 ubv[na].x, ubv[na].y);
            }
            __syncthreads();
            if (s + 2 < 16) { cpB2(s + 2); cp_commit(); }
        }

        float2 bias2[4], w3v[4];
#pragma unroll
        for (int na = 0; na < 4; ++na) {
            bias2[na] = *(const float2*)&sB2[wnl + na * 8 + 2 * c];
            w3v[na]   = *(const float2*)&sW3[wnl + na * 8 + 2 * c];
        }
#pragma unroll
        for (int ma = 0; ma < 4; ++ma) {
            float p0 = 0.f, p1 = 0.f;
#pragma unroll
            for (int na = 0; na < 4; ++na) {
                p0 += fmaxf(cf[ma][na][0] + bias2[na].x, 0.f) * w3v[na].x
                    + fmaxf(cf[ma][na][1] + bias2[na].y, 0.f) * w3v[na].y;
                p1 += fmaxf(cf[ma][na][2] + bias2[na].x, 0.f) * w3v[na].x
                    + fmaxf(cf[ma][na][3] + bias2[na].y, 0.f) * w3v[na].y;
            }
            p0 += __shfl_xor_sync(0xffffffffu, p0, 1);
            p0 += __shfl_xor_sync(0xffffffffu, p0, 2);
            p1 += __shfl_xor_sync(0xffffffffu, p1, 1);
            p1 += __shfl_xor_sync(0xffffffffu, p1, 2);
            if (c == 0) {
                const int rl = ma * 16 + r;
                psum[rl * 8 + warp] = p0;
                psum[(rl + 8) * 8 + warp] = p1;
            }
        }
        __syncthreads();
        if (tid < 64) {
            const int gm = bm + tid;
            if (gm < M) {
                float s = 0.f;
#pragma unroll
                for (int w = 0; w < 8; ++w) s += psum[tid * 8 + w];
                outv[gm] = s + __ldg(b3);
            }
        }
    }
}

// ============================================================================
extern "C" void kernel_launch(void* const* d_in, const int* in_sizes, int n_in,
                              void* d_out, int out_size)
{
    const float* x     = (const float*)d_in[0];
    const void*  eidx  = d_in[1];
    const float* eattr = (const float*)d_in[2];
    const float* Wn    = (const float*)d_in[3];
    const float* bnode = (const float*)d_in[4];
    const float* We    = (const float*)d_in[5];
    const float* be    = (const float*)d_in[6];
    const float* W1    = (const float*)d_in[7];
    const float* b1    = (const float*)d_in[8];
    const float* W2    = (const float*)d_in[9];
    const float* b2    = (const float*)d_in[10];
    const float* W3    = (const float*)d_in[11];
    const float* b3    = (const float*)d_in[12];
    float* out = (float*)d_out;

    // launches: 0 detect, 1 conv, 2 prep, 3 np (node+Pab fused), 4 fq
    detect_idx_kernel<<<1, 256>>>(eidx);
    conv_idx_kernel<<<(kEdges + 255) / 256, 256>>>(eidx);
    prep_kernel<<<13880, 256>>>(x, Wn, We, W1, W2, b1);

    cudaFuncSetAttribute(np_kernel,
                         cudaFuncAttributeMaxDynamicSharedMemorySize, NP_SMEM);
    np_kernel<<<(kNodes + 127) / 128, 256, NP_SMEM>>>(bnode, kNodes);

    cudaFuncSetAttribute(fq_kernel,
                         cudaFuncAttributeMaxDynamicSharedMemorySize, FQ_SMEM);
    fq_kernel<<<(kEdges + 63) / 64, 256, FQ_SMEM>>>(eattr, be, b2, W3, b3, out, kEdges);
}

// round 14
// speedup vs baseline: 1.2992x; 1.2992x over previous
#include <cuda_runtime.h>
#include <cuda_fp16.h>
#include <cstdint>

namespace {
constexpr int kNodes = 50000;
constexpr int kEdges = 500000;
constexpr int MM_SMEM = 50176;    // mm_kernel: sA 3*8K | sB 3*8K | bias 512B
// fq_kernel: sQ 16*4K=64K | sEf 4*4K=16K | stream 2*16K=32K  => 114688
constexpr int FQ_SMEM = 114688;
}

// ============================================================================
// Static scratch. All half matrices K-PERMUTED per 16-group:
//   kperm(k) = (k&~15) + ((k&7)>>1)*4 + (k&1) + ((k>>3)&1)*2
// ============================================================================
__device__ __half g_node_f[(size_t)kNodes * 128];
__device__ __half g_pab[(size_t)kNodes * 1024];   // [node_f@W1a + b1 | node_f@W1b]
__device__ __half g_xt[(size_t)kNodes * 128];
__device__ __half g_wnt[128 * 128];
__device__ __half g_wet[128 * 64];
__device__ __half g_w1ab[1024 * 128];
__device__ __half g_w1c[512 * 128];
__device__ __half g_w2t[256 * 512];
__device__ float  g_bias1024[1024];
__device__ int    g_src[kEdges];
__device__ int    g_dst[kEdges];
__device__ int    g_is64;

// ============================================================================
// Helpers
// ============================================================================
__device__ __forceinline__ void cp_async16(void* smem, const void* gmem) {
    uint32_t s;
    asm("{ .reg .u64 t; cvta.to.shared.u64 t, %1; cvt.u32.u64 %0, t; }" : "=r"(s) : "l"(smem));
    asm volatile("cp.async.cg.shared.global [%0], [%1], 16;\n" :: "r"(s), "l"(gmem));
}
__device__ __forceinline__ void cp_commit() { asm volatile("cp.async.commit_group;\n"); }
__device__ __forceinline__ void cp_wait0()  { asm volatile("cp.async.wait_group 0;\n" ::: "memory"); }
__device__ __forceinline__ void cp_wait1()  { asm volatile("cp.async.wait_group 1;\n" ::: "memory"); }

__device__ __forceinline__ void mma16816(float* cc, uint32_t a0, uint32_t a1,
                                         uint32_t a2, uint32_t a3,
                                         uint32_t b0, uint32_t b1) {
    asm volatile(
        "mma.sync.aligned.m16n8k16.row.col.f32.f16.f16.f32 "
        "{%0,%1,%2,%3}, {%4,%5,%6,%7}, {%8,%9}, {%0,%1,%2,%3};"
        : "+f"(cc[0]), "+f"(cc[1]), "+f"(cc[2]), "+f"(cc[3])
        : "r"(a0), "r"(a1), "r"(a2), "r"(a3), "r"(b0), "r"(b1));
}
__host__ __device__ __forceinline__ int kperm(int k) {
    return (k & ~15) + (((k & 7) >> 1) << 2) + (k & 1) + (((k >> 3) & 1) << 1);
}

// ============================================================================
// Index prep
// ============================================================================
__global__ void detect_idx_kernel(const void* idx) {
    const int t = threadIdx.x;            // 256 threads, 1 value each
    const long long v = ((const long long*)idx)[t];
    int bad = (v < 0) || (v >= kNodes);
    int cnt = __syncthreads_count(bad);
    if (t == 0) g_is64 = (cnt == 0);
}
__global__ void conv_idx_kernel(const void* idx) {
    int i = blockIdx.x * blockDim.x + threadIdx.x;
    if (i >= kEdges) return;
    int s, d;
    if (g_is64) {
        const long long* p = (const long long*)idx;
        s = (int)p[i]; d = (int)p[kEdges + i];
    } else {
        const int* p = (const int*)idx;
        s = p[i]; d = p[kEdges + i];
    }
    g_src[i] = s; g_dst[i] = d;
}

// All weight/activation preps in one launch (block-range dispatch).
// x path vectorized: kperm maps pairs (2k,2k+1) to adjacent positions,
// so one float2 load -> one half2 store.
//  [0,12500)      x -> g_xt        (2 elems/thread)
//  [12500,12564)  Wn -> g_wnt
//  [12564,12596)  We -> g_wet
//  [12596,13108)  W2 -> g_w2t
//  [13108,13620)  W1 rows 0..255 -> g_w1ab
//  [13620,13876)  W1 rows 256..383 -> g_w1c
//  [13876,13880)  b1 -> g_bias1024
__global__ void prep_kernel(const float* __restrict__ x,
                            const float* __restrict__ Wn, const float* __restrict__ We,
                            const float* __restrict__ W1, const float* __restrict__ W2,
                            const float* __restrict__ b1) {
    const int b = blockIdx.x;
    const int t = threadIdx.x;
    if (b < 12500) {
        int i2 = b * 256 + t;                // pair index
        int row = i2 >> 6, kp = (i2 & 63) * 2;
        float2 v = *(const float2*)(x + (size_t)row * 128 + kp);
        __half2 h; h.x = __float2half_rn(v.x); h.y = __float2half_rn(v.y);
        *(__half2*)(g_xt + (size_t)row * 128 + kperm(kp)) = h;
    } else if (b < 12564) {
        int i = (b - 12500) * 256 + t;       // K=128,N=128
        int k = i >> 7, n = i & 127;
        g_wnt[n * 128 + kperm(k)] = __float2half_rn(Wn[i]);
    } else if (b < 12596) {
        int i = (b - 12564) * 256 + t;       // K=64,N=128
        int k = i >> 7, n = i & 127;
        g_wet[n * 64 + kperm(k)] = __float2half_rn(We[i]);
    } else if (b < 13108) {
        int i = (b - 12596) * 256 + t;       // K=512,N=256
        int k = i >> 8, n = i & 255;
        g_w2t[(size_t)n * 512 + kperm(k)] = __float2half_rn(W2[i]);
    } else if (b < 13620) {
        int i = (b - 13108) * 256 + t;       // n = i>>7 (0..1023), k = i&127
        int n = i >> 7, k = i & 127;
        int srcRow = (n < 512) ? k : (128 + k);
        int srcCol = (n < 512) ? n : (n - 512);
        g_w1ab[(size_t)n * 128 + kperm(k)] = __float2half_rn(W1[(size_t)srcRow * 512 + srcCol]);
    } else if (b < 13876) {
        int i = (b - 13620) * 256 + t;       // n = i>>7 (0..511), k = i&127
        int n = i >> 7, k = i & 127;
        g_w1c[(size_t)n * 128 + kperm(k)] = __float2half_rn(W1[(size_t)(256 + k) * 512 + n]);
    } else {
        int i = (b - 13876) * 256 + t;
        if (i < 1024) g_bias1024[i] = (i < 512) ? b1[i] : 0.f;
    }
}

// ============================================================================
// FP16 mma GEMM (node-side): C[M,N] = act(A@Bt^T + bias), fp16 kperm store.
// ============================================================================
template <int K, int N, bool RELU>
__global__ __launch_bounds__(256, 2)
void mm_kernel(const __half* __restrict__ A, const __half* __restrict__ Bt,
               const float* __restrict__ bias, __half* __restrict__ Cmat, int M)
{
    constexpr int NS = K / 32;
    extern __shared__ char smc[];
    char*  sAc   = smc;
    char*  sBc   = smc + 24576;
    float* sBias = (float*)(smc + 49152);

    const int tid  = threadIdx.x;
    const int lane = tid & 31;
    const int warp = tid >> 5;
    const int r    = lane >> 2;
    const int c    = lane & 3;
    const int wm   = (warp >> 2) * 64;
    const int wnl  = (warp & 3) * 32;
    const int bn   = blockIdx.x * 128;
    const int bm   = blockIdx.y * 128;

    if (tid < 128) sBias[tid] = bias ? __ldg(bias + bn + tid) : 0.f;
    __syncthreads();

    auto load_stage = [&](int s) {
        const int buf = s % 3;
        const int k0 = s * 32;
        char* dA = sAc + buf * 8192;
        char* dB = sBc + buf * 8192;
#pragma unroll
        for (int t = 0; t < 2; ++t) {
            int idx = tid + t * 256;
            int row = idx >> 2, j = idx & 3;
            cp_async16(dA + row * 64 + ((j ^ (row & 3)) << 4),
                       A + (size_t)min(bm + row, M - 1) * K + k0 + j * 8);
        }
#pragma unroll
        for (int t = 0; t < 2; ++t) {
            int idx = tid + t * 256;
            int n = idx >> 2, j = idx & 3;
            cp_async16(dB + n * 64 + ((j ^ (n & 3)) << 4),
                       Bt + (size_t)(bn + n) * K + k0 + j * 8);
        }
    };

    float cf[4][4][4] = {};
    load_stage(0); cp_commit();
    if (NS > 1) { load_stage(1); cp_commit(); }

    for (int s = 0; s < NS; ++s) {
        if (s + 1 < NS) cp_wait1(); else cp_wait0();
        __syncthreads();
        if (s + 2 < NS) { load_stage(s + 2); cp_commit(); }

        const char* fA = sAc + (s % 3) * 8192;
        const char* fB = sBc + (s % 3) * 8192;
#pragma unroll
        for (int g = 0; g < 2; ++g) {
            const int coff = (((g * 2 + (c >> 1)) ^ (r & 3)) << 4) + (c & 1) * 8;
            uint2 ua[4], ub_[4], ubv[4];
#pragma unroll
            for (int ma = 0; ma < 4; ++ma) {
                const int row0 = wm + ma * 16 + r;
                ua[ma]  = *(const uint2*)(fA + row0 * 64 + coff);
                ub_[ma] = *(const uint2*)(fA + (row0 + 8) * 64 + coff);
            }
#pragma unroll
            for (int na = 0; na < 4; ++na)
                ubv[na] = *(const uint2*)(fB + (wnl + na * 8 + r) * 64 + coff);
#pragma unroll
            for (int ma = 0; ma < 4; ++ma)
#pragma unroll
                for (int na = 0; na < 4; ++na)
                    mma16816(cf[ma][na], ua[ma].x, ub_[ma].x, ua[ma].y, ub_[ma].y,
                             ubv[na].x, ubv[na].y);
        }
    }
    __syncthreads();

    float2 bias2[4];
#pragma unroll
    for (int na = 0; na < 4; ++na)
        bias2[na] = *(const float2*)&sBias[wnl + na * 8 + 2 * c];

#pragma unroll
    for (int ma = 0; ma < 4; ++ma) {
        const int row0 = bm + wm + ma * 16 + r;
        const int row1 = row0 + 8;
#pragma unroll
        for (int na = 0; na < 4; ++na) {
            const int nloc = wnl + na * 8 + 2 * c;
            const int pcol = bn + (nloc & ~15) + 4 * c + 2 * ((nloc >> 3) & 1);
            float v0 = cf[ma][na][0] + bias2[na].x;
            float v1 = cf[ma][na][1] + bias2[na].y;
            float v2 = cf[ma][na][2] + bias2[na].x;
            float v3 = cf[ma][na][3] + bias2[na].y;
            if (RELU) {
                v0 = fmaxf(v0, 0.f); v1 = fmaxf(v1, 0.f);
                v2 = fmaxf(v2, 0.f); v3 = fmaxf(v3, 0.f);
            }
            if (row0 < M) {
                __half2 h; h.x = __float2half_rn(v0); h.y = __float2half_rn(v1);
                *(__half2*)(Cmat + (size_t)row0 * N + pcol) = h;
            }
            if (row1 < M) {
                __half2 h; h.x = __float2half_rn(v2); h.y = __float2half_rn(v3);
                *(__half2*)(Cmat + (size_t)row1 * N + pcol) = h;
            }
        }
    }
}

// ============================================================================
// Fused edge kernel: per-CTA 64 edges, everything in smem.
//  P0: edge_f = relu(eattr@We+be)          -> sEf (4 stage-tiles, 16KB)
//  P1: Q = edge_f @ W1c                    -> sQ  (16 stage-tiles, 64KB)
//  P2: A = relu(Pa[src]+Pb[dst]+Q) in place; out = relu(A@W2+b2).W3 + b3
// Stage-tile layout (64 rows x 64B): addr = tile + row*64 + ((j^(row&3))<<4).
// Phase-2 Pa/Pb gather prefetch is SINGLE-depth (register budget: 128/thread).
// ============================================================================
__global__ __launch_bounds__(256, 2)
void fq_kernel(const float* __restrict__ eattr,
               const float* __restrict__ be, const float* __restrict__ b2,
               const float* __restrict__ W3, const float* __restrict__ b3,
               float* __restrict__ outv, int M)
{
    extern __shared__ char smc[];
    char* sQ  = smc;            // 16 x 4096
    char* sEf = smc + 65536;    // 4 x 4096
    char* sStr = smc + 81920;   // 32768 stream region

    const int tid  = threadIdx.x;
    const int lane = tid & 31;
    const int warp = tid >> 5;
    const int r    = lane >> 2;
    const int c    = lane & 3;
    const int bm   = blockIdx.x * 64;

    auto stsC = [&](char* tiles, int row, int nloc, float v0, float v1) {
        const int pcol = (nloc & ~15) + 4 * c + 2 * ((nloc >> 3) & 1);
        const int stage = pcol >> 5;
        const int byte = (pcol & 31) * 2;
        const int j = byte >> 4;
        __half2 h; h.x = __float2half_rn(v0); h.y = __float2half_rn(v1);
        *(__half2*)(tiles + stage * 4096 + row * 64 + ((j ^ (row & 3)) << 4) + (byte & 15)) = h;
    };

    // ================= Phase 0: edge encoder =================
    {
        char* sA0 = sStr;             // 2 x 4096
        char* sB0 = sStr + 8192;      // 2 x 8192
        float* sBe = (float*)(sStr + 24576);   // 128 f32

        if (tid < 128) sBe[tid] = __ldg(be + tid);
#pragma unroll
        for (int t = 0; t < 4; ++t) {
            int idx = tid + t * 256;
            int stage = idx >> 9, rem = idx & 511;
            int n = rem >> 2, j = rem & 3;
            cp_async16(sB0 + stage * 8192 + n * 64 + ((j ^ (n & 3)) << 4),
                       g_wet + (size_t)n * 64 + stage * 32 + j * 8);
        }
        cp_commit();
        {
            const int row = tid >> 2, seg = tid & 3;
            const int e = min(bm + row, M - 1);
            const float* es = eattr + (size_t)e * 64 + seg * 16;
            float ff[16];
#pragma unroll
            for (int q4 = 0; q4 < 4; ++q4) {
                float4 v = __ldg((const float4*)(es + q4 * 4));
                ff[q4 * 4] = v.x; ff[q4 * 4 + 1] = v.y;
                ff[q4 * 4 + 2] = v.z; ff[q4 * 4 + 3] = v.w;
            }
            __half arr[16];
#pragma unroll
            for (int kk = 0; kk < 16; ++kk) {
                int p = (((kk & 7) >> 1) << 2) + (kk & 1) + (((kk >> 3) & 1) << 1);
                arr[p] = __float2half_rn(ff[kk]);
            }
            const int stage = seg >> 1, jb = (seg & 1) * 2;
            char* base = sA0 + stage * 4096 + row * 64;
            *(uint4*)(base + (((jb    ) ^ (row & 3)) << 4)) = *(uint4*)arr;
            *(uint4*)(base + (((jb + 1) ^ (row & 3)) << 4)) = *(uint4*)(arr + 8);
        }
        cp_wait0();
        __syncthreads();

        const int wm0 = (warp >> 2) * 32;
        const int wnl0 = (warp & 3) * 32;
        float cf0[2][4][4] = {};
#pragma unroll
        for (int s0 = 0; s0 < 2; ++s0) {
            const char* fA = sA0 + s0 * 4096;
            const char* fB = sB0 + s0 * 8192;
#pragma unroll
            for (int g = 0; g < 2; ++g) {
                const int coff = (((g * 2 + (c >> 1)) ^ (r & 3)) << 4) + (c & 1) * 8;
                uint2 ua[2], ub_[2], ubv[4];
#pragma unroll
                for (int ma = 0; ma < 2; ++ma) {
                    const int row0 = wm0 + ma * 16 + r;
                    ua[ma]  = *(const uint2*)(fA + row0 * 64 + coff);
                    ub_[ma] = *(const uint2*)(fA + (row0 + 8) * 64 + coff);
                }
#pragma unroll
                for (int na = 0; na < 4; ++na)
                    ubv[na] = *(const uint2*)(fB + (wnl0 + na * 8 + r) * 64 + coff);
#pragma unroll
                for (int ma = 0; ma < 2; ++ma)
#pragma unroll
                    for (int na = 0; na < 4; ++na)
                        mma16816(cf0[ma][na], ua[ma].x, ub_[ma].x, ua[ma].y, ub_[ma].y,
                                 ubv[na].x, ubv[na].y);
            }
        }
        __syncthreads();
#pragma unroll
        for (int ma = 0; ma < 2; ++ma) {
            const int row0 = wm0 + ma * 16 + r;
#pragma unroll
            for (int na = 0; na < 4; ++na) {
                const int nloc = wnl0 + na * 8 + 2 * c;
                float b0 = sBe[nloc], b1v = sBe[nloc + 1];
                stsC(sEf, row0,     nloc, fmaxf(cf0[ma][na][0] + b0, 0.f),
                                          fmaxf(cf0[ma][na][1] + b1v, 0.f));
                stsC(sEf, row0 + 8, nloc, fmaxf(cf0[ma][na][2] + b0, 0.f),
                                          fmaxf(cf0[ma][na][3] + b1v, 0.f));
            }
        }
        __syncthreads();
    }

    // ================= Phase 1: Q = edge_f @ W1c (2 passes of N=256) ========
    {
        const int wnl = warp * 32;
        auto cpB1 = [&](int np, int s) {
            char* dB = sStr + (s & 1) * 16384;
#pragma unroll
            for (int t = 0; t < 4; ++t) {
                int idx = tid + t * 256;
                int n = idx >> 2, j = idx & 3;
                cp_async16(dB + n * 64 + ((j ^ (n & 3)) << 4),
                           g_w1c + (size_t)(np * 256 + n) * 128 + s * 32 + j * 8);
            }
        };
#pragma unroll
        for (int np = 0; np < 2; ++np) {
            float cf1[4][4][4] = {};
            cpB1(np, 0); cp_commit();
            cpB1(np, 1); cp_commit();
#pragma unroll
            for (int s = 0; s < 4; ++s) {
                if (s + 1 < 4) cp_wait1(); else cp_wait0();
                __syncthreads();
                const char* fA = sEf + s * 4096;
                const char* fB = sStr + (s & 1) * 16384;
#pragma unroll
                for (int g = 0; g < 2; ++g) {
                    const int coff = (((g * 2 + (c >> 1)) ^ (r & 3)) << 4) + (c & 1) * 8;
                    uint2 ua[4], ub_[4], ubv[4];
#pragma unroll
                    for (int ma = 0; ma < 4; ++ma) {
                        const int row0 = ma * 16 + r;
                        ua[ma]  = *(const uint2*)(fA + row0 * 64 + coff);
                        ub_[ma] = *(const uint2*)(fA + (row0 + 8) * 64 + coff);
                    }
#pragma unroll
                    for (int na = 0; na < 4; ++na)
                        ubv[na] = *(const uint2*)(fB + (wnl + na * 8 + r) * 64 + coff);
#pragma unroll
                    for (int ma = 0; ma < 4; ++ma)
#pragma unroll
                        for (int na = 0; na < 4; ++na)
                            mma16816(cf1[ma][na], ua[ma].x, ub_[ma].x, ua[ma].y, ub_[ma].y,
                                     ubv[na].x, ubv[na].y);
                }
                __syncthreads();
                if (s + 2 < 4) { cpB1(np, s + 2); cp_commit(); }
            }
#pragma unroll
            for (int ma = 0; ma < 4; ++ma) {
                const int row0 = ma * 16 + r;
#pragma unroll
                for (int na = 0; na < 4; ++na) {
                    const int nloc = np * 256 + wnl + na * 8 + 2 * c;
                    stsC(sQ, row0,     nloc, cf1[ma][na][0], cf1[ma][na][1]);
                    stsC(sQ, row0 + 8, nloc, cf1[ma][na][2], cf1[ma][na][3]);
                }
            }
            __syncthreads();
        }
    }

    // ================= Phase 2: W2 + W3 =================
    {
        float* sB2 = (float*)sEf;            // 256 f32
        float* sW3 = (float*)(sEf + 1024);   // 256 f32
        float* psum = (float*)(sEf + 2048);  // 64 x 8 f32
        sB2[tid] = __ldg(b2 + tid);
        sW3[tid] = __ldg(W3 + tid);

        const int row = tid >> 2, j = tid & 3;
        const int e = min(bm + row, M - 1);
        const __half* paP = g_pab + (size_t)g_src[e] * 1024;
        const __half* pbP = g_pab + (size_t)g_dst[e] * 1024 + 512;
        char* qaddrBase = sQ + row * 64 + ((j ^ (row & 3)) << 4);

        uint4 ra, rb;
        auto ldgA = [&](int s) {
            ra = __ldg((const uint4*)(paP + s * 32 + j * 8));
            rb = __ldg((const uint4*)(pbP + s * 32 + j * 8));
        };
        auto finA = [&](int s) {
            uint4 q4 = *(uint4*)(qaddrBase + s * 4096);
            const half2* qh = (const half2*)&q4;
            const half2* ha = (const half2*)&ra;
            const half2* hb = (const half2*)&rb;
            half2 v[4];
            const half2 z = __float2half2_rn(0.f);
#pragma unroll
            for (int i = 0; i < 4; ++i)
                v[i] = __hmax2(__hadd2(__hadd2(qh[i], ha[i]), hb[i]), z);
            *(uint4*)(qaddrBase + s * 4096) = *(uint4*)v;
        };
        auto cpB2 = [&](int s) {
            char* dB = sStr + (s & 1) * 16384;
#pragma unroll
            for (int t = 0; t < 4; ++t) {
                int idx = tid + t * 256;
                int n = idx >> 2, j2 = idx & 3;
                cp_async16(dB + n * 64 + ((j2 ^ (n & 3)) << 4),
                           g_w2t + (size_t)n * 512 + s * 32 + j2 * 8);
            }
        };

        const int wnl = warp * 32;
        float cf[4][4][4] = {};

        ldgA(0);
        cpB2(0); cp_commit();
        cpB2(1); cp_commit();

#pragma unroll 1
        for (int s = 0; s < 16; ++s) {
            finA(s);
            if (s + 1 < 16) ldgA(s + 1);
            if (s + 1 < 16) cp_wait1(); else cp_wait0();
            __syncthreads();
            const char* fA = sQ + s * 4096;
            const char* fB = sStr + (s & 1) * 16384;
#pragma unroll
            for (int g = 0; g < 2; ++g) {
                const int coff = (((g * 2 + (c >> 1)) ^ (r & 3)) << 4) + (c & 1) * 8;
                uint2 ua[4], ub_[4], ubv[4];
#pragma unroll
                for (int ma = 0; ma < 4; ++ma) {
                    const int row0 = ma * 16 + r;
                    ua[ma]  = *(const uint2*)(fA + row0 * 64 + coff);
                    ub_[ma] = *(const uint2*)(fA + (row0 + 8) * 64 + coff);
                }
#pragma unroll
                for (int na = 0; na < 4; ++na)
                    ubv[na] = *(const uint2*)(fB + (wnl + na * 8 + r) * 64 + coff);
#pragma unroll
                for (int ma = 0; ma < 4; ++ma)
#pragma unroll
                    for (int na = 0; na < 4; ++na)
                        mma16816(cf[ma][na], ua[ma].x, ub_[ma].x, ua[ma].y, ub_[ma].y,
                                 ubv[na].x, ubv[na].y);
            }
            __syncthreads();
            if (s + 2 < 16) { cpB2(s + 2); cp_commit(); }
        }

        float2 bias2[4], w3v[4];
#pragma unroll
        for (int na = 0; na < 4; ++na) {
            bias2[na] = *(const float2*)&sB2[wnl + na * 8 + 2 * c];
            w3v[na]   = *(const float2*)&sW3[wnl + na * 8 + 2 * c];
        }
#pragma unroll
        for (int ma = 0; ma < 4; ++ma) {
            float p0 = 0.f, p1 = 0.f;
#pragma unroll
            for (int na = 0; na < 4; ++na) {
                p0 += fmaxf(cf[ma][na][0] + bias2[na].x, 0.f) * w3v[na].x
                    + fmaxf(cf[ma][na][1] + bias2[na].y, 0.f) * w3v[na].y;
                p1 += fmaxf(cf[ma][na][2] + bias2[na].x, 0.f) * w3v[na].x
                    + fmaxf(cf[ma][na][3] + bias2[na].y, 0.f) * w3v[na].y;
            }
            p0 += __shfl_xor_sync(0xffffffffu, p0, 1);
            p0 += __shfl_xor_sync(0xffffffffu, p0, 2);
            p1 += __shfl_xor_sync(0xffffffffu, p1, 1);
            p1 += __shfl_xor_sync(0xffffffffu, p1, 2);
            if (c == 0) {
                const int rl = ma * 16 + r;
                psum[rl * 8 + warp] = p0;
                psum[(rl + 8) * 8 + warp] = p1;
            }
        }
        __syncthreads();
        if (tid < 64) {
            const int gm = bm + tid;
            if (gm < M) {
                float s = 0.f;
#pragma unroll
                for (int w = 0; w < 8; ++w) s += psum[tid * 8 + w];
                outv[gm] = s + __ldg(b3);
            }
        }
    }
}

// ============================================================================
extern "C" void kernel_launch(void* const* d_in, const int* in_sizes, int n_in,
                              void* d_out, int out_size)
{
    const float* x     = (const float*)d_in[0];
    const void*  eidx  = d_in[1];
    const float* eattr = (const float*)d_in[2];
    const float* Wn    = (const float*)d_in[3];
    const float* bnode = (const float*)d_in[4];
    const float* We    = (const float*)d_in[5];
    const float* be    = (const float*)d_in[6];
    const float* W1    = (const float*)d_in[7];
    const float* b1    = (const float*)d_in[8];
    const float* W2    = (const float*)d_in[9];
    const float* b2    = (const float*)d_in[10];
    const float* W3    = (const float*)d_in[11];
    const float* b3    = (const float*)d_in[12];
    float* out = (float*)d_out;

    __half *p_node, *p_pab, *p_xt, *p_wnt, *p_w1ab;
    float* p_b1024;
    cudaGetSymbolAddress((void**)&p_node, g_node_f);
    cudaGetSymbolAddress((void**)&p_pab, g_pab);
    cudaGetSymbolAddress((void**)&p_xt, g_xt);
    cudaGetSymbolAddress((void**)&p_wnt, g_wnt);
    cudaGetSymbolAddress((void**)&p_w1ab, g_w1ab);
    cudaGetSymbolAddress((void**)&p_b1024, g_bias1024);

    // launches: 0 detect, 1 conv, 2 prep, 3 node_enc, 4 pab, 5 fq
    detect_idx_kernel<<<1, 256>>>(eidx);
    conv_idx_kernel<<<(kEdges + 255) / 256, 256>>>(eidx);
    prep_kernel<<<13880, 256>>>(x, Wn, We, W1, W2, b1);

    // node encoder [50000,128]
    cudaFuncSetAttribute(mm_kernel<128, 128, true>,
                         cudaFuncAttributeMaxDynamicSharedMemorySize, MM_SMEM);
    mm_kernel<128, 128, true><<<dim3(1, (kNodes + 127) / 128), 256, MM_SMEM>>>(
        p_xt, p_wnt, bnode, p_node, kNodes);

    // Pab = node_f @ [W1a|W1b] + [b1|0]   [50000,1024]
    cudaFuncSetAttribute(mm_kernel<128, 1024, false>,
                         cudaFuncAttributeMaxDynamicSharedMemorySize, MM_SMEM);
    mm_kernel<128, 1024, false><<<dim3(8, (kNodes + 127) / 128), 256, MM_SMEM>>>(
        p_node, p_w1ab, p_b1024, p_pab, kNodes);

    // fused edge pipeline
    cudaFuncSetAttribute(fq_kernel,
                         cudaFuncAttributeMaxDynamicSharedMemorySize, FQ_SMEM);
    fq_kernel<<<(kEdges + 63) / 64, 256, FQ_SMEM>>>(eattr, be, b2, W3, b3, out, kEdges);
}

// round 15
// speedup vs baseline: 1.3570x; 1.0445x over previous
#include <cuda_runtime.h>
#include <cuda_fp16.h>
#include <cstdint>

namespace {
constexpr int kNodes = 50000;
constexpr int kEdges = 500000;
constexpr int MM_SMEM = 50176;    // mm_kernel: sA 3*8K | sB 3*8K | bias 512B
// fq_kernel: sQ 16*4K=64K | sEf 4*4K=16K | stream 2*16K=32K  => 114688
constexpr int FQ_SMEM = 114688;
// front_kernel block ranges
constexpr int FB_CONV = (kEdges + 255) / 256;      // 1954
constexpr int FB_X    = FB_CONV + 12500;           // x -> g_xt
constexpr int FB_WN   = FB_X + 64;
constexpr int FB_WE   = FB_WN + 32;
constexpr int FB_W2   = FB_WE + 512;
constexpr int FB_W1AB = FB_W2 + 512;
constexpr int FB_W1C  = FB_W1AB + 256;
constexpr int FB_B1   = FB_W1C + 4;
}

// ============================================================================
// Static scratch. All half matrices K-PERMUTED per 16-group:
//   kperm(k) = (k&~15) + ((k&7)>>1)*4 + (k&1) + ((k>>3)&1)*2
// ============================================================================
__device__ __half g_node_f[(size_t)kNodes * 128];
__device__ __half g_pab[(size_t)kNodes * 1024];   // [node_f@W1a + b1 | node_f@W1b]
__device__ __half g_xt[(size_t)kNodes * 128];
__device__ __half g_wnt[128 * 128];
__device__ __half g_wet[128 * 64];
__device__ __half g_w1ab[1024 * 128];
__device__ __half g_w1c[512 * 128];
__device__ __half g_w2t[256 * 512];
__device__ float  g_bias1024[1024];
__device__ int    g_src[kEdges];
__device__ int    g_dst[kEdges];

// ============================================================================
// Helpers
// ============================================================================
__device__ __forceinline__ void cp_async16(void* smem, const void* gmem) {
    uint32_t s;
    asm("{ .reg .u64 t; cvta.to.shared.u64 t, %1; cvt.u32.u64 %0, t; }" : "=r"(s) : "l"(smem));
    asm volatile("cp.async.cg.shared.global [%0], [%1], 16;\n" :: "r"(s), "l"(gmem));
}
__device__ __forceinline__ void cp_commit() { asm volatile("cp.async.commit_group;\n"); }
__device__ __forceinline__ void cp_wait0()  { asm volatile("cp.async.wait_group 0;\n" ::: "memory"); }
__device__ __forceinline__ void cp_wait1()  { asm volatile("cp.async.wait_group 1;\n" ::: "memory"); }

__device__ __forceinline__ void mma16816(float* cc, uint32_t a0, uint32_t a1,
                                         uint32_t a2, uint32_t a3,
                                         uint32_t b0, uint32_t b1) {
    asm volatile(
        "mma.sync.aligned.m16n8k16.row.col.f32.f16.f16.f32 "
        "{%0,%1,%2,%3}, {%4,%5,%6,%7}, {%8,%9}, {%0,%1,%2,%3};"
        : "+f"(cc[0]), "+f"(cc[1]), "+f"(cc[2]), "+f"(cc[3])
        : "r"(a0), "r"(a1), "r"(a2), "r"(a3), "r"(b0), "r"(b1));
}
__host__ __device__ __forceinline__ int kperm(int k) {
    return (k & ~15) + (((k & 7) >> 1) << 2) + (k & 1) + (((k >> 3) & 1) << 1);
}

// ============================================================================
// Front kernel: index conversion + all weight/activation preps, ONE launch.
//  [0, FB_CONV)        edge_index -> g_src/g_dst (dtype self-detected per block
//                      from the first 256 int64 words — L2-hot, ~free)
//  [FB_CONV, FB_X)     x -> g_xt (float2->half2, kperm pair-adjacent)
//  [FB_X, FB_WN)       Wn -> g_wnt
//  [FB_WN, FB_WE)      We -> g_wet
//  [FB_WE, FB_W2)      W2 -> g_w2t
//  [FB_W2, FB_W1AB)    W1 rows 0..255 -> g_w1ab
//  [FB_W1AB, FB_W1C)   W1 rows 256..383 -> g_w1c
//  [FB_W1C, FB_B1)     b1 -> g_bias1024
// ============================================================================
__global__ void front_kernel(const void* __restrict__ idx, const float* __restrict__ x,
                             const float* __restrict__ Wn, const float* __restrict__ We,
                             const float* __restrict__ W1, const float* __restrict__ W2,
                             const float* __restrict__ b1) {
    const int b = blockIdx.x;
    const int t = threadIdx.x;
    if (b < FB_CONV) {
        __shared__ int s_is64;
        const long long v = ((const long long*)idx)[t];
        int bad = (v < 0) || (v >= kNodes);
        int cnt = __syncthreads_count(bad);
        if (t == 0) s_is64 = (cnt == 0);
        __syncthreads();
        const int is64 = s_is64;
        const int i = b * 256 + t;
        if (i < kEdges) {
            int s, d;
            if (is64) {
                const long long* p = (const long long*)idx;
                s = (int)p[i]; d = (int)p[kEdges + i];
            } else {
                const int* p = (const int*)idx;
                s = p[i]; d = p[kEdges + i];
            }
            g_src[i] = s; g_dst[i] = d;
        }
    } else if (b < FB_X) {
        int i2 = (b - FB_CONV) * 256 + t;    // pair index
        int row = i2 >> 6, kp = (i2 & 63) * 2;
        float2 v = *(const float2*)(x + (size_t)row * 128 + kp);
        __half2 h; h.x = __float2half_rn(v.x); h.y = __float2half_rn(v.y);
        *(__half2*)(g_xt + (size_t)row * 128 + kperm(kp)) = h;
    } else if (b < FB_WN) {
        int i = (b - FB_X) * 256 + t;        // K=128,N=128
        int k = i >> 7, n = i & 127;
        g_wnt[n * 128 + kperm(k)] = __float2half_rn(Wn[i]);
    } else if (b < FB_WE) {
        int i = (b - FB_WN) * 256 + t;       // K=64,N=128
        int k = i >> 7, n = i & 127;
        g_wet[n * 64 + kperm(k)] = __float2half_rn(We[i]);
    } else if (b < FB_W2) {
        int i = (b - FB_WE) * 256 + t;       // K=512,N=256
        int k = i >> 8, n = i & 255;
        g_w2t[(size_t)n * 512 + kperm(k)] = __float2half_rn(W2[i]);
    } else if (b < FB_W1AB) {
        int i = (b - FB_W2) * 256 + t;       // n = i>>7 (0..1023), k = i&127
        int n = i >> 7, k = i & 127;
        int srcRow = (n < 512) ? k : (128 + k);
        int srcCol = (n < 512) ? n : (n - 512);
        g_w1ab[(size_t)n * 128 + kperm(k)] = __float2half_rn(W1[(size_t)srcRow * 512 + srcCol]);
    } else if (b < FB_W1C) {
        int i = (b - FB_W1AB) * 256 + t;     // n = i>>7 (0..511), k = i&127
        int n = i >> 7, k = i & 127;
        g_w1c[(size_t)n * 128 + kperm(k)] = __float2half_rn(W1[(size_t)(256 + k) * 512 + n]);
    } else {
        int i = (b - FB_W1C) * 256 + t;
        if (i < 1024) g_bias1024[i] = (i < 512) ? b1[i] : 0.f;
    }
}

// ============================================================================
// FP16 mma GEMM (node-side): C[M,N] = act(A@Bt^T + bias), fp16 kperm store.
// ============================================================================
template <int K, int N, bool RELU>
__global__ __launch_bounds__(256, 2)
void mm_kernel(const __half* __restrict__ A, const __half* __restrict__ Bt,
               const float* __restrict__ bias, __half* __restrict__ Cmat, int M)
{
    constexpr int NS = K / 32;
    extern __shared__ char smc[];
    char*  sAc   = smc;
    char*  sBc   = smc + 24576;
    float* sBias = (float*)(smc + 49152);

    const int tid  = threadIdx.x;
    const int lane = tid & 31;
    const int warp = tid >> 5;
    const int r    = lane >> 2;
    const int c    = lane & 3;
    const int wm   = (warp >> 2) * 64;
    const int wnl  = (warp & 3) * 32;
    const int bn   = blockIdx.x * 128;
    const int bm   = blockIdx.y * 128;

    if (tid < 128) sBias[tid] = bias ? __ldg(bias + bn + tid) : 0.f;
    __syncthreads();

    auto load_stage = [&](int s) {
        const int buf = s % 3;
        const int k0 = s * 32;
        char* dA = sAc + buf * 8192;
        char* dB = sBc + buf * 8192;
#pragma unroll
        for (int t = 0; t < 2; ++t) {
            int idx = tid + t * 256;
            int row = idx >> 2, j = idx & 3;
            cp_async16(dA + row * 64 + ((j ^ (row & 3)) << 4),
                       A + (size_t)min(bm + row, M - 1) * K + k0 + j * 8);
        }
#pragma unroll
        for (int t = 0; t < 2; ++t) {
            int idx = tid + t * 256;
            int n = idx >> 2, j = idx & 3;
            cp_async16(dB + n * 64 + ((j ^ (n & 3)) << 4),
                       Bt + (size_t)(bn + n) * K + k0 + j * 8);
        }
    };

    float cf[4][4][4] = {};
    load_stage(0); cp_commit();
    if (NS > 1) { load_stage(1); cp_commit(); }

    for (int s = 0; s < NS; ++s) {
        if (s + 1 < NS) cp_wait1(); else cp_wait0();
        __syncthreads();
        if (s + 2 < NS) { load_stage(s + 2); cp_commit(); }

        const char* fA = sAc + (s % 3) * 8192;
        const char* fB = sBc + (s % 3) * 8192;
#pragma unroll
        for (int g = 0; g < 2; ++g) {
            const int coff = (((g * 2 + (c >> 1)) ^ (r & 3)) << 4) + (c & 1) * 8;
            uint2 ua[4], ub_[4], ubv[4];
#pragma unroll
            for (int ma = 0; ma < 4; ++ma) {
                const int row0 = wm + ma * 16 + r;
                ua[ma]  = *(const uint2*)(fA + row0 * 64 + coff);
                ub_[ma] = *(const uint2*)(fA + (row0 + 8) * 64 + coff);
            }
#pragma unroll
            for (int na = 0; na < 4; ++na)
                ubv[na] = *(const uint2*)(fB + (wnl + na * 8 + r) * 64 + coff);
#pragma unroll
            for (int ma = 0; ma < 4; ++ma)
#pragma unroll
                for (int na = 0; na < 4; ++na)
                    mma16816(cf[ma][na], ua[ma].x, ub_[ma].x, ua[ma].y, ub_[ma].y,
                             ubv[na].x, ubv[na].y);
        }
    }
    __syncthreads();

    float2 bias2[4];
#pragma unroll
    for (int na = 0; na < 4; ++na)
        bias2[na] = *(const float2*)&sBias[wnl + na * 8 + 2 * c];

#pragma unroll
    for (int ma = 0; ma < 4; ++ma) {
        const int row0 = bm + wm + ma * 16 + r;
        const int row1 = row0 + 8;
#pragma unroll
        for (int na = 0; na < 4; ++na) {
            const int nloc = wnl + na * 8 + 2 * c;
            const int pcol = bn + (nloc & ~15) + 4 * c + 2 * ((nloc >> 3) & 1);
            float v0 = cf[ma][na][0] + bias2[na].x;
            float v1 = cf[ma][na][1] + bias2[na].y;
            float v2 = cf[ma][na][2] + bias2[na].x;
            float v3 = cf[ma][na][3] + bias2[na].y;
            if (RELU) {
                v0 = fmaxf(v0, 0.f); v1 = fmaxf(v1, 0.f);
                v2 = fmaxf(v2, 0.f); v3 = fmaxf(v3, 0.f);
            }
            if (row0 < M) {
                __half2 h; h.x = __float2half_rn(v0); h.y = __float2half_rn(v1);
                *(__half2*)(Cmat + (size_t)row0 * N + pcol) = h;
            }
            if (row1 < M) {
                __half2 h; h.x = __float2half_rn(v2); h.y = __float2half_rn(v3);
                *(__half2*)(Cmat + (size_t)row1 * N + pcol) = h;
            }
        }
    }
}

// ============================================================================
// Fused edge kernel: per-CTA 64 edges, everything in smem.
//  P0: edge_f = relu(eattr@We+be)          -> sEf (4 stage-tiles, 16KB)
//  P1: Q = edge_f @ W1c                    -> sQ  (16 stage-tiles, 64KB)
//  P2: A = relu(Pa[src]+Pb[dst]+Q) in place; out = relu(A@W2+b2).W3 + b3
// Stage-tile layout (64 rows x 64B): addr = tile + row*64 + ((j^(row&3))<<4).
// Phase 2 uses ONE barrier per stage: each warp cp.asyncs its OWN 32 B-rows
// (read region == write region per warp), so the read->overwrite hazard on the
// B double buffer is warp-private and needs no CTA barrier.
// ============================================================================
__global__ __launch_bounds__(256, 2)
void fq_kernel(const float* __restrict__ eattr,
               const float* __restrict__ be, const float* __restrict__ b2,
               const float* __restrict__ W3, const float* __restrict__ b3,
               float* __restrict__ outv, int M)
{
    extern __shared__ char smc[];
    char* sQ  = smc;            // 16 x 4096
    char* sEf = smc + 65536;    // 4 x 4096
    char* sStr = smc + 81920;   // 32768 stream region

    const int tid  = threadIdx.x;
    const int lane = tid & 31;
    const int warp = tid >> 5;
    const int r    = lane >> 2;
    const int c    = lane & 3;
    const int bm   = blockIdx.x * 64;

    auto stsC = [&](char* tiles, int row, int nloc, float v0, float v1) {
        const int pcol = (nloc & ~15) + 4 * c + 2 * ((nloc >> 3) & 1);
        const int stage = pcol >> 5;
        const int byte = (pcol & 31) * 2;
        const int j = byte >> 4;
        __half2 h; h.x = __float2half_rn(v0); h.y = __float2half_rn(v1);
        *(__half2*)(tiles + stage * 4096 + row * 64 + ((j ^ (row & 3)) << 4) + (byte & 15)) = h;
    };

    // ================= Phase 0: edge encoder =================
    {
        char* sA0 = sStr;             // 2 x 4096
        char* sB0 = sStr + 8192;      // 2 x 8192
        float* sBe = (float*)(sStr + 24576);   // 128 f32

        if (tid < 128) sBe[tid] = __ldg(be + tid);
#pragma unroll
        for (int t = 0; t < 4; ++t) {
            int idx = tid + t * 256;
            int stage = idx >> 9, rem = idx & 511;
            int n = rem >> 2, j = rem & 3;
            cp_async16(sB0 + stage * 8192 + n * 64 + ((j ^ (n & 3)) << 4),
                       g_wet + (size_t)n * 64 + stage * 32 + j * 8);
        }
        cp_commit();
        {
            const int row = tid >> 2, seg = tid & 3;
            const int e = min(bm + row, M - 1);
            const float* es = eattr + (size_t)e * 64 + seg * 16;
            float ff[16];
#pragma unroll
            for (int q4 = 0; q4 < 4; ++q4) {
                float4 v = __ldg((const float4*)(es + q4 * 4));
                ff[q4 * 4] = v.x; ff[q4 * 4 + 1] = v.y;
                ff[q4 * 4 + 2] = v.z; ff[q4 * 4 + 3] = v.w;
            }
            __half arr[16];
#pragma unroll
            for (int kk = 0; kk < 16; ++kk) {
                int p = (((kk & 7) >> 1) << 2) + (kk & 1) + (((kk >> 3) & 1) << 1);
                arr[p] = __float2half_rn(ff[kk]);
            }
            const int stage = seg >> 1, jb = (seg & 1) * 2;
            char* base = sA0 + stage * 4096 + row * 64;
            *(uint4*)(base + (((jb    ) ^ (row & 3)) << 4)) = *(uint4*)arr;
            *(uint4*)(base + (((jb + 1) ^ (row & 3)) << 4)) = *(uint4*)(arr + 8);
        }
        cp_wait0();
        __syncthreads();

        const int wm0 = (warp >> 2) * 32;
        const int wnl0 = (warp & 3) * 32;
        float cf0[2][4][4] = {};
#pragma unroll
        for (int s0 = 0; s0 < 2; ++s0) {
            const char* fA = sA0 + s0 * 4096;
            const char* fB = sB0 + s0 * 8192;
#pragma unroll
            for (int g = 0; g < 2; ++g) {
                const int coff = (((g * 2 + (c >> 1)) ^ (r & 3)) << 4) + (c & 1) * 8;
                uint2 ua[2], ub_[2], ubv[4];
#pragma unroll
                for (int ma = 0; ma < 2; ++ma) {
                    const int row0 = wm0 + ma * 16 + r;
                    ua[ma]  = *(const uint2*)(fA + row0 * 64 + coff);
                    ub_[ma] = *(const uint2*)(fA + (row0 + 8) * 64 + coff);
                }
#pragma unroll
                for (int na = 0; na < 4; ++na)
                    ubv[na] = *(const uint2*)(fB + (wnl0 + na * 8 + r) * 64 + coff);
#pragma unroll
                for (int ma = 0; ma < 2; ++ma)
#pragma unroll
                    for (int na = 0; na < 4; ++na)
                        mma16816(cf0[ma][na], ua[ma].x, ub_[ma].x, ua[ma].y, ub_[ma].y,
                                 ubv[na].x, ubv[na].y);
            }
        }
        __syncthreads();
#pragma unroll
        for (int ma = 0; ma < 2; ++ma) {
            const int row0 = wm0 + ma * 16 + r;
#pragma unroll
            for (int na = 0; na < 4; ++na) {
                const int nloc = wnl0 + na * 8 + 2 * c;
                float b0 = sBe[nloc], b1v = sBe[nloc + 1];
                stsC(sEf, row0,     nloc, fmaxf(cf0[ma][na][0] + b0, 0.f),
                                          fmaxf(cf0[ma][na][1] + b1v, 0.f));
                stsC(sEf, row0 + 8, nloc, fmaxf(cf0[ma][na][2] + b0, 0.f),
                                          fmaxf(cf0[ma][na][3] + b1v, 0.f));
            }
        }
        __syncthreads();
    }

    // ================= Phase 1: Q = edge_f @ W1c (2 passes of N=256) ========
    {
        const int wnl = warp * 32;
        auto cpB1 = [&](int np, int s) {
            char* dB = sStr + (s & 1) * 16384;
#pragma unroll
            for (int t = 0; t < 4; ++t) {
                int idx = tid + t * 256;
                int n = idx >> 2, j = idx & 3;
                cp_async16(dB + n * 64 + ((j ^ (n & 3)) << 4),
                           g_w1c + (size_t)(np * 256 + n) * 128 + s * 32 + j * 8);
            }
        };
#pragma unroll
        for (int np = 0; np < 2; ++np) {
            float cf1[4][4][4] = {};
            cpB1(np, 0); cp_commit();
            cpB1(np, 1); cp_commit();
#pragma unroll
            for (int s = 0; s < 4; ++s) {
                if (s + 1 < 4) cp_wait1(); else cp_wait0();
                __syncthreads();
                const char* fA = sEf + s * 4096;
                const char* fB = sStr + (s & 1) * 16384;
#pragma unroll
                for (int g = 0; g < 2; ++g) {
                    const int coff = (((g * 2 + (c >> 1)) ^ (r & 3)) << 4) + (c & 1) * 8;
                    uint2 ua[4], ub_[4], ubv[4];
#pragma unroll
                    for (int ma = 0; ma < 4; ++ma) {
                        const int row0 = ma * 16 + r;
                        ua[ma]  = *(const uint2*)(fA + row0 * 64 + coff);
                        ub_[ma] = *(const uint2*)(fA + (row0 + 8) * 64 + coff);
                    }
#pragma unroll
                    for (int na = 0; na < 4; ++na)
                        ubv[na] = *(const uint2*)(fB + (wnl + na * 8 + r) * 64 + coff);
#pragma unroll
                    for (int ma = 0; ma < 4; ++ma)
#pragma unroll
                        for (int na = 0; na < 4; ++na)
                            mma16816(cf1[ma][na], ua[ma].x, ub_[ma].x, ua[ma].y, ub_[ma].y,
                                     ubv[na].x, ubv[na].y);
                }
                __syncthreads();
                if (s + 2 < 4) { cpB1(np, s + 2); cp_commit(); }
            }
#pragma unroll
            for (int ma = 0; ma < 4; ++ma) {
                const int row0 = ma * 16 + r;
#pragma unroll
                for (int na = 0; na < 4; ++na) {
                    const int nloc = np * 256 + wnl + na * 8 + 2 * c;
                    stsC(sQ, row0,     nloc, cf1[ma][na][0], cf1[ma][na][1]);
                    stsC(sQ, row0 + 8, nloc, cf1[ma][na][2], cf1[ma][na][3]);
                }
            }
            __syncthreads();
        }
    }

    // ================= Phase 2: W2 + W3 (single barrier per stage) ==========
    {
        float* sB2 = (float*)sEf;            // 256 f32
        float* sW3 = (float*)(sEf + 1024);   // 256 f32
        float* psum = (float*)(sEf + 2048);  // 64 x 8 f32
        sB2[tid] = __ldg(b2 + tid);
        sW3[tid] = __ldg(W3 + tid);

        const int row = tid >> 2, j = tid & 3;
        const int e = min(bm + row, M - 1);
        const __half* paP = g_pab + (size_t)g_src[e] * 1024;
        const __half* pbP = g_pab + (size_t)g_dst[e] * 1024 + 512;
        char* qaddrBase = sQ + row * 64 + ((j ^ (row & 3)) << 4);
        const int wnl = warp * 32;

        uint4 ra, rb;
        auto ldgA = [&](int s) {
            ra = __ldg((const uint4*)(paP + s * 32 + j * 8));
            rb = __ldg((const uint4*)(pbP + s * 32 + j * 8));
        };
        auto finA = [&](int s) {
            uint4 q4 = *(uint4*)(qaddrBase + s * 4096);
            const half2* qh = (const half2*)&q4;
            const half2* ha = (const half2*)&ra;
            const half2* hb = (const half2*)&rb;
            half2 v[4];
            const half2 z = __float2half2_rn(0.f);
#pragma unroll
            for (int i = 0; i < 4; ++i)
                v[i] = __hmax2(__hadd2(__hadd2(qh[i], ha[i]), hb[i]), z);
            *(uint4*)(qaddrBase + s * 4096) = *(uint4*)v;
        };
        // per-warp B loader: warp loads ONLY its own 32 rows (== its read set)
        auto cpB2w = [&](int s) {
            char* dB = sStr + (s & 1) * 16384;
#pragma unroll
            for (int t = 0; t < 4; ++t) {
                int idx = lane + t * 32;            // 0..127
                int nl = idx >> 2, j2 = idx & 3;    // nl 0..31
                int n = wnl + nl;
                cp_async16(dB + n * 64 + ((j2 ^ (n & 3)) << 4),
                           g_w2t + (size_t)n * 512 + s * 32 + j2 * 8);
            }
        };

        float cf[4][4][4] = {};

        ldgA(0);
        cpB2w(0); cp_commit();
        cpB2w(1); cp_commit();
        finA(0);            // Pa/Pb(0) latency exposed once per CTA
        ldgA(1);

#pragma unroll 1
        for (int s = 0; s < 16; ++s) {
            if (s + 1 < 16) cp_wait1(); else cp_wait0();
            __syncthreads();        // finA(s) from all warps + own B(s) ready
            const char* fA = sQ + s * 4096;
            const char* fB = sStr + (s & 1) * 16384;
#pragma unroll
            for (int g = 0; g < 2; ++g) {
                const int coff = (((g * 2 + (c >> 1)) ^ (r & 3)) << 4) + (c & 1) * 8;
                uint2 ua[4], ub_[4], ubv[4];
#pragma unroll
                for (int ma = 0; ma < 4; ++ma) {
                    const int row0 = ma * 16 + r;
                    ua[ma]  = *(const uint2*)(fA + row0 * 64 + coff);
                    ub_[ma] = *(const uint2*)(fA + (row0 + 8) * 64 + coff);
                }
#pragma unroll
                for (int na = 0; na < 4; ++na)
                    ubv[na] = *(const uint2*)(fB + (wnl + na * 8 + r) * 64 + coff);
#pragma unroll
                for (int ma = 0; ma < 4; ++ma)
#pragma unroll
                    for (int na = 0; na < 4; ++na)
                        mma16816(cf[ma][na], ua[ma].x, ub_[ma].x, ua[ma].y, ub_[ma].y,
                                 ubv[na].x, ubv[na].y);
            }
            // overwrite of this warp's fB region: warp-private, no barrier
            if (s + 2 < 16) { cpB2w(s + 2); cp_commit(); }
            if (s + 1 < 16) {
                finA(s + 1);               // writes sQ stage s+1 (read after next barrier)
                if (s + 2 < 16) ldgA(s + 2);
            }
        }

        float2 bias2[4], w3v[4];
#pragma unroll
        for (int na = 0; na < 4; ++na) {
            bias2[na] = *(const float2*)&sB2[wnl + na * 8 + 2 * c];
            w3v[na]   = *(const float2*)&sW3[wnl + na * 8 + 2 * c];
        }
#pragma unroll
        for (int ma = 0; ma < 4; ++ma) {
            float p0 = 0.f, p1 = 0.f;
#pragma unroll
            for (int na = 0; na < 4; ++na) {
                p0 += fmaxf(cf[ma][na][0] + bias2[na].x, 0.f) * w3v[na].x
                    + fmaxf(cf[ma][na][1] + bias2[na].y, 0.f) * w3v[na].y;
                p1 += fmaxf(cf[ma][na][2] + bias2[na].x, 0.f) * w3v[na].x
                    + fmaxf(cf[ma][na][3] + bias2[na].y, 0.f) * w3v[na].y;
            }
            p0 += __shfl_xor_sync(0xffffffffu, p0, 1);
            p0 += __shfl_xor_sync(0xffffffffu, p0, 2);
            p1 += __shfl_xor_sync(0xffffffffu, p1, 1);
            p1 += __shfl_xor_sync(0xffffffffu, p1, 2);
            if (c == 0) {
                const int rl = ma * 16 + r;
                psum[rl * 8 + warp] = p0;
                psum[(rl + 8) * 8 + warp] = p1;
            }
        }
        __syncthreads();
        if (tid < 64) {
            const int gm = bm + tid;
            if (gm < M) {
                float s = 0.f;
#pragma unroll
                for (int w = 0; w < 8; ++w) s += psum[tid * 8 + w];
                outv[gm] = s + __ldg(b3);
            }
        }
    }
}

// ============================================================================
extern "C" void kernel_launch(void* const* d_in, const int* in_sizes, int n_in,
                              void* d_out, int out_size)
{
    const float* x     = (const float*)d_in[0];
    const void*  eidx  = d_in[1];
    const float* eattr = (const float*)d_in[2];
    const float* Wn    = (const float*)d_in[3];
    const float* bnode = (const float*)d_in[4];
    const float* We    = (const float*)d_in[5];
    const float* be    = (const float*)d_in[6];
    const float* W1    = (const float*)d_in[7];
    const float* b1    = (const float*)d_in[8];
    const float* W2    = (const float*)d_in[9];
    const float* b2    = (const float*)d_in[10];
    const float* W3    = (const float*)d_in[11];
    const float* b3    = (const float*)d_in[12];
    float* out = (float*)d_out;

    __half *p_node, *p_pab, *p_xt, *p_wnt, *p_w1ab;
    float* p_b1024;
    cudaGetSymbolAddress((void**)&p_node, g_node_f);
    cudaGetSymbolAddress((void**)&p_pab, g_pab);
    cudaGetSymbolAddress((void**)&p_xt, g_xt);
    cudaGetSymbolAddress((void**)&p_wnt, g_wnt);
    cudaGetSymbolAddress((void**)&p_w1ab, g_w1ab);
    cudaGetSymbolAddress((void**)&p_b1024, g_bias1024);

    // launches: 0 front (idx+preps), 1 node_enc, 2 pab, 3 fq
    front_kernel<<<FB_B1, 256>>>(eidx, x, Wn, We, W1, W2, b1);

    // node encoder [50000,128]
    cudaFuncSetAttribute(mm_kernel<128, 128, true>,
                         cudaFuncAttributeMaxDynamicSharedMemorySize, MM_SMEM);
    mm_kernel<128, 128, true><<<dim3(1, (kNodes + 127) / 128), 256, MM_SMEM>>>(
        p_xt, p_wnt, bnode, p_node, kNodes);

    // Pab = node_f @ [W1a|W1b] + [b1|0]   [50000,1024]
    cudaFuncSetAttribute(mm_kernel<128, 1024, false>,
                         cudaFuncAttributeMaxDynamicSharedMemorySize, MM_SMEM);
    mm_kernel<128, 1024, false><<<dim3(8, (kNodes + 127) / 128), 256, MM_SMEM>>>(
        p_node, p_w1ab, p_b1024, p_pab, kNodes);

    // fused edge pipeline
    cudaFuncSetAttribute(fq_kernel,
                         cudaFuncAttributeMaxDynamicSharedMemorySize, FQ_SMEM);
    fq_kernel<<<(kEdges + 63) / 64, 256, FQ_SMEM>>>(eattr, be, b2, W3, b3, out, kEdges);
}

// round 16
// speedup vs baseline: 1.4835x; 1.0933x over previous
#include <cuda_runtime.h>
#include <cuda_fp16.h>
#include <cstdint>

namespace {
constexpr int kNodes = 50000;
constexpr int kEdges = 500000;
constexpr int MM_SMEM = 50176;    // mm_kernel: sA 3*8K | sB 3*8K | bias 512B
// fq_kernel: sQ 16*4K=64K | sEf 4*4K=16K | stream 2*16K=32K  => 114688
constexpr int FQ_SMEM = 114688;
// front_kernel block ranges
constexpr int FB_CONV = (kEdges + 255) / 256;      // 1954
constexpr int FB_X    = FB_CONV + 12500;           // x -> g_xt
constexpr int FB_WN   = FB_X + 64;
constexpr int FB_WE   = FB_WN + 32;
constexpr int FB_W2   = FB_WE + 512;
constexpr int FB_W1AB = FB_W2 + 512;
constexpr int FB_W1C  = FB_W1AB + 256;
constexpr int FB_B1   = FB_W1C + 4;
}

// ============================================================================
// Static scratch. All half matrices PLAIN K-major (ldmatrix defines fragment
// distribution; no gmem permutation needed anymore).
// ============================================================================
__device__ __half g_node_f[(size_t)kNodes * 128];
__device__ __half g_pab[(size_t)kNodes * 1024];   // [node_f@W1a + b1 | node_f@W1b]
__device__ __half g_xt[(size_t)kNodes * 128];
__device__ __half g_wnt[128 * 128];
__device__ __half g_wet[128 * 64];
__device__ __half g_w1ab[1024 * 128];
__device__ __half g_w1c[512 * 128];
__device__ __half g_w2t[256 * 512];
__device__ float  g_bias1024[1024];
__device__ int    g_src[kEdges];
__device__ int    g_dst[kEdges];

// ============================================================================
// Helpers
// ============================================================================
__device__ __forceinline__ uint32_t smem_u32(const void* p) {
    uint32_t a;
    asm("{ .reg .u64 t; cvta.to.shared.u64 t, %1; cvt.u32.u64 %0, t; }" : "=r"(a) : "l"(p));
    return a;
}
__device__ __forceinline__ void cp_async16(void* smem, const void* gmem) {
    uint32_t s;
    asm("{ .reg .u64 t; cvta.to.shared.u64 t, %1; cvt.u32.u64 %0, t; }" : "=r"(s) : "l"(smem));
    asm volatile("cp.async.cg.shared.global [%0], [%1], 16;\n" :: "r"(s), "l"(gmem));
}
__device__ __forceinline__ void cp_commit() { asm volatile("cp.async.commit_group;\n"); }
__device__ __forceinline__ void cp_wait0()  { asm volatile("cp.async.wait_group 0;\n" ::: "memory"); }
__device__ __forceinline__ void cp_wait1()  { asm volatile("cp.async.wait_group 1;\n" ::: "memory"); }

__device__ __forceinline__ void mma16816(float* cc, uint32_t a0, uint32_t a1,
                                         uint32_t a2, uint32_t a3,
                                         uint32_t b0, uint32_t b1) {
    asm volatile(
        "mma.sync.aligned.m16n8k16.row.col.f32.f16.f16.f32 "
        "{%0,%1,%2,%3}, {%4,%5,%6,%7}, {%8,%9}, {%0,%1,%2,%3};"
        : "+f"(cc[0]), "+f"(cc[1]), "+f"(cc[2]), "+f"(cc[3])
        : "r"(a0), "r"(a1), "r"(a2), "r"(a3), "r"(b0), "r"(b1));
}
__device__ __forceinline__ void ldsm4(uint32_t* r, uint32_t addr) {
    asm volatile("ldmatrix.sync.aligned.m8n8.x4.shared.b16 {%0,%1,%2,%3}, [%4];"
                 : "=r"(r[0]), "=r"(r[1]), "=r"(r[2]), "=r"(r[3]) : "r"(addr));
}
// smem chunk swizzle: 16B chunk j of row stored at j ^ ((row>>1)&3)
__device__ __forceinline__ int swz(int row, int j) {
    return (j ^ ((row >> 1) & 3)) << 4;
}

// ============================================================================
// Front kernel: index conversion + all weight/activation preps, ONE launch.
// ============================================================================
__global__ void front_kernel(const void* __restrict__ idx, const float* __restrict__ x,
                             const float* __restrict__ Wn, const float* __restrict__ We,
                             const float* __restrict__ W1, const float* __restrict__ W2,
                             const float* __restrict__ b1) {
    const int b = blockIdx.x;
    const int t = threadIdx.x;
    if (b < FB_CONV) {
        __shared__ int s_is64;
        const long long v = ((const long long*)idx)[t];
        int bad = (v < 0) || (v >= kNodes);
        int cnt = __syncthreads_count(bad);
        if (t == 0) s_is64 = (cnt == 0);
        __syncthreads();
        const int is64 = s_is64;
        const int i = b * 256 + t;
        if (i < kEdges) {
            int s, d;
            if (is64) {
                const long long* p = (const long long*)idx;
                s = (int)p[i]; d = (int)p[kEdges + i];
            } else {
                const int* p = (const int*)idx;
                s = p[i]; d = p[kEdges + i];
            }
            g_src[i] = s; g_dst[i] = d;
        }
    } else if (b < FB_X) {
        int i2 = (b - FB_CONV) * 256 + t;    // pair index, plain copy
        float2 v = ((const float2*)x)[i2];
        __half2 h; h.x = __float2half_rn(v.x); h.y = __float2half_rn(v.y);
        ((__half2*)g_xt)[i2] = h;
    } else if (b < FB_WN) {
        int i = (b - FB_X) * 256 + t;        // K=128,N=128
        int k = i >> 7, n = i & 127;
        g_wnt[n * 128 + k] = __float2half_rn(Wn[i]);
    } else if (b < FB_WE) {
        int i = (b - FB_WN) * 256 + t;       // K=64,N=128
        int k = i >> 7, n = i & 127;
        g_wet[n * 64 + k] = __float2half_rn(We[i]);
    } else if (b < FB_W2) {
        int i = (b - FB_WE) * 256 + t;       // K=512,N=256
        int k = i >> 8, n = i & 255;
        g_w2t[(size_t)n * 512 + k] = __float2half_rn(W2[i]);
    } else if (b < FB_W1AB) {
        int i = (b - FB_W2) * 256 + t;       // n = i>>7 (0..1023), k = i&127
        int n = i >> 7, k = i & 127;
        int srcRow = (n < 512) ? k : (128 + k);
        int srcCol = (n < 512) ? n : (n - 512);
        g_w1ab[(size_t)n * 128 + k] = __float2half_rn(W1[(size_t)srcRow * 512 + srcCol]);
    } else if (b < FB_W1C) {
        int i = (b - FB_W1AB) * 256 + t;     // n = i>>7 (0..511), k = i&127
        int n = i >> 7, k = i & 127;
        g_w1c[(size_t)n * 128 + k] = __float2half_rn(W1[(size_t)(256 + k) * 512 + n]);
    } else {
        int i = (b - FB_W1C) * 256 + t;
        if (i < 1024) g_bias1024[i] = (i < 512) ? b1[i] : 0.f;
    }
}

// ============================================================================
// FP16 mma GEMM (node-side): C[M,N] = act(A@Bt^T + bias), plain fp16 store.
// ldmatrix fragment loading; smem tiles row*64B, chunk swizzle swz().
// ============================================================================
template <int K, int N, bool RELU>
__global__ __launch_bounds__(256, 2)
void mm_kernel(const __half* __restrict__ A, const __half* __restrict__ Bt,
               const float* __restrict__ bias, __half* __restrict__ Cmat, int M)
{
    constexpr int NS = K / 32;
    extern __shared__ char smc[];
    char*  sAc   = smc;
    char*  sBc   = smc + 24576;
    float* sBias = (float*)(smc + 49152);

    const int tid  = threadIdx.x;
    const int lane = tid & 31;
    const int warp = tid >> 5;
    const int r    = lane >> 2;
    const int c    = lane & 3;
    const int rr   = lane & 7;
    const int sub  = lane >> 3;
    const int arow = rr + ((sub & 1) << 3);   // A ldmatrix row-in-fragment
    const int acs  = sub >> 1;                // A ldmatrix chunk select
    const int brow = rr + ((sub >> 1) << 3);  // B ldmatrix row-in-pair
    const int bcs  = sub & 1;                 // B ldmatrix chunk select
    const int wm   = (warp >> 2) * 64;
    const int wnl  = (warp & 3) * 32;
    const int bn   = blockIdx.x * 128;
    const int bm   = blockIdx.y * 128;
    const uint32_t uA = smem_u32(sAc);
    const uint32_t uB = smem_u32(sBc);

    if (tid < 128) sBias[tid] = bias ? __ldg(bias + bn + tid) : 0.f;
    __syncthreads();

    auto load_stage = [&](int s) {
        const int buf = s % 3;
        const int k0 = s * 32;
        char* dA = sAc + buf * 8192;
        char* dB = sBc + buf * 8192;
#pragma unroll
        for (int t = 0; t < 2; ++t) {
            int idx = tid + t * 256;
            int row = idx >> 2, j = idx & 3;
            cp_async16(dA + row * 64 + swz(row, j),
                       A + (size_t)min(bm + row, M - 1) * K + k0 + j * 8);
        }
#pragma unroll
        for (int t = 0; t < 2; ++t) {
            int idx = tid + t * 256;
            int n = idx >> 2, j = idx & 3;
            cp_async16(dB + n * 64 + swz(n, j),
                       Bt + (size_t)(bn + n) * K + k0 + j * 8);
        }
    };

    float cf[4][4][4] = {};
    load_stage(0); cp_commit();
    if (NS > 1) { load_stage(1); cp_commit(); }

    for (int s = 0; s < NS; ++s) {
        if (s + 1 < NS) cp_wait1(); else cp_wait0();
        __syncthreads();
        if (s + 2 < NS) { load_stage(s + 2); cp_commit(); }

        const uint32_t fA = uA + (s % 3) * 8192;
        const uint32_t fB = uB + (s % 3) * 8192;
#pragma unroll
        for (int g = 0; g < 2; ++g) {
            uint32_t av[4][4], bv[2][4];
#pragma unroll
            for (int ma = 0; ma < 4; ++ma) {
                const int row = wm + ma * 16 + arow;
                ldsm4(av[ma], fA + row * 64 + swz(row, 2 * g + acs));
            }
#pragma unroll
            for (int p = 0; p < 2; ++p) {
                const int n = wnl + p * 16 + brow;
                ldsm4(bv[p], fB + n * 64 + swz(n, 2 * g + bcs));
            }
#pragma unroll
            for (int ma = 0; ma < 4; ++ma)
#pragma unroll
                for (int na = 0; na < 4; ++na)
                    mma16816(cf[ma][na], av[ma][0], av[ma][1], av[ma][2], av[ma][3],
                             bv[na >> 1][(na & 1) * 2], bv[na >> 1][(na & 1) * 2 + 1]);
        }
    }
    __syncthreads();

    float2 bias2[4];
#pragma unroll
    for (int na = 0; na < 4; ++na)
        bias2[na] = *(const float2*)&sBias[wnl + na * 8 + 2 * c];

#pragma unroll
    for (int ma = 0; ma < 4; ++ma) {
        const int row0 = bm + wm + ma * 16 + r;
        const int row1 = row0 + 8;
#pragma unroll
        for (int na = 0; na < 4; ++na) {
            const int pcol = bn + wnl + na * 8 + 2 * c;    // plain column
            float v0 = cf[ma][na][0] + bias2[na].x;
            float v1 = cf[ma][na][1] + bias2[na].y;
            float v2 = cf[ma][na][2] + bias2[na].x;
            float v3 = cf[ma][na][3] + bias2[na].y;
            if (RELU) {
                v0 = fmaxf(v0, 0.f); v1 = fmaxf(v1, 0.f);
                v2 = fmaxf(v2, 0.f); v3 = fmaxf(v3, 0.f);
            }
            if (row0 < M) {
                __half2 h; h.x = __float2half_rn(v0); h.y = __float2half_rn(v1);
                *(__half2*)(Cmat + (size_t)row0 * N + pcol) = h;
            }
            if (row1 < M) {
                __half2 h; h.x = __float2half_rn(v2); h.y = __float2half_rn(v3);
                *(__half2*)(Cmat + (size_t)row1 * N + pcol) = h;
            }
        }
    }
}

// ============================================================================
// Fused edge kernel (per-CTA 64 edges; phases as before, ldmatrix fragments).
// Stage-tile (64 rows x 64B): addr = tile + row*64 + swz(row, j) + within.
// ============================================================================
__global__ __launch_bounds__(256, 2)
void fq_kernel(const float* __restrict__ eattr,
               const float* __restrict__ be, const float* __restrict__ b2,
               const float* __restrict__ W3, const float* __restrict__ b3,
               float* __restrict__ outv, int M)
{
    extern __shared__ char smc[];
    char* sQ  = smc;            // 16 x 4096
    char* sEf = smc + 65536;    // 4 x 4096
    char* sStr = smc + 81920;   // 32768 stream region

    const int tid  = threadIdx.x;
    const int lane = tid & 31;
    const int warp = tid >> 5;
    const int r    = lane >> 2;
    const int c    = lane & 3;
    const int rr   = lane & 7;
    const int sub  = lane >> 3;
    const int arow = rr + ((sub & 1) << 3);
    const int acs  = sub >> 1;
    const int brow = rr + ((sub >> 1) << 3);
    const int bcs  = sub & 1;
    const int bm   = blockIdx.x * 64;
    const uint32_t uQ  = smem_u32(sQ);
    const uint32_t uEf = smem_u32(sEf);
    const uint32_t uStr = smem_u32(sStr);

    // accumulator -> stage-tile store (plain cols)
    auto stsC = [&](char* tiles, int row, int nloc, float v0, float v1) {
        const int stage = nloc >> 5;
        const int byte = (nloc & 31) * 2;
        const int j = byte >> 4;
        __half2 h; h.x = __float2half_rn(v0); h.y = __float2half_rn(v1);
        *(__half2*)(tiles + stage * 4096 + row * 64 + swz(row, j) + (byte & 15)) = h;
    };

    // ================= Phase 0: edge encoder =================
    {
        char* sA0 = sStr;             // 2 x 4096
        char* sB0 = sStr + 8192;      // 2 x 8192
        float* sBe = (float*)(sStr + 24576);   // 128 f32

        if (tid < 128) sBe[tid] = __ldg(be + tid);
#pragma unroll
        for (int t = 0; t < 4; ++t) {
            int idx = tid + t * 256;
            int stage = idx >> 9, rem = idx & 511;
            int n = rem >> 2, j = rem & 3;
            cp_async16(sB0 + stage * 8192 + n * 64 + swz(n, j),
                       g_wet + (size_t)n * 64 + stage * 32 + j * 8);
        }
        cp_commit();
        {
            const int row = tid >> 2, seg = tid & 3;
            const int e = min(bm + row, M - 1);
            const float* es = eattr + (size_t)e * 64 + seg * 16;
            __half arr[16];
#pragma unroll
            for (int q4 = 0; q4 < 4; ++q4) {
                float4 v = __ldg((const float4*)(es + q4 * 4));
                arr[q4 * 4]     = __float2half_rn(v.x);
                arr[q4 * 4 + 1] = __float2half_rn(v.y);
                arr[q4 * 4 + 2] = __float2half_rn(v.z);
                arr[q4 * 4 + 3] = __float2half_rn(v.w);
            }
            const int stage = seg >> 1, jb = (seg & 1) * 2;
            char* base = sA0 + stage * 4096 + row * 64;
            *(uint4*)(base + swz(row, jb))     = *(uint4*)arr;
            *(uint4*)(base + swz(row, jb + 1)) = *(uint4*)(arr + 8);
        }
        cp_wait0();
        __syncthreads();

        const int wm0 = (warp >> 2) * 32;
        const int wnl0 = (warp & 3) * 32;
        const uint32_t uA0 = uStr;
        const uint32_t uB0 = uStr + 8192;
        float cf0[2][4][4] = {};
#pragma unroll
        for (int s0 = 0; s0 < 2; ++s0) {
            const uint32_t fA = uA0 + s0 * 4096;
            const uint32_t fB = uB0 + s0 * 8192;
#pragma unroll
            for (int g = 0; g < 2; ++g) {
                uint32_t av[2][4], bv[2][4];
#pragma unroll
                for (int ma = 0; ma < 2; ++ma) {
                    const int row = wm0 + ma * 16 + arow;
                    ldsm4(av[ma], fA + row * 64 + swz(row, 2 * g + acs));
                }
#pragma unroll
                for (int p = 0; p < 2; ++p) {
                    const int n = wnl0 + p * 16 + brow;
                    ldsm4(bv[p], fB + n * 64 + swz(n, 2 * g + bcs));
                }
#pragma unroll
                for (int ma = 0; ma < 2; ++ma)
#pragma unroll
                    for (int na = 0; na < 4; ++na)
                        mma16816(cf0[ma][na], av[ma][0], av[ma][1], av[ma][2], av[ma][3],
                                 bv[na >> 1][(na & 1) * 2], bv[na >> 1][(na & 1) * 2 + 1]);
            }
        }
        __syncthreads();
#pragma unroll
        for (int ma = 0; ma < 2; ++ma) {
            const int row0 = wm0 + ma * 16 + r;
#pragma unroll
            for (int na = 0; na < 4; ++na) {
                const int nloc = wnl0 + na * 8 + 2 * c;
                float b0 = sBe[nloc], b1v = sBe[nloc + 1];
                stsC(sEf, row0,     nloc, fmaxf(cf0[ma][na][0] + b0, 0.f),
                                          fmaxf(cf0[ma][na][1] + b1v, 0.f));
                stsC(sEf, row0 + 8, nloc, fmaxf(cf0[ma][na][2] + b0, 0.f),
                                          fmaxf(cf0[ma][na][3] + b1v, 0.f));
            }
        }
        __syncthreads();
    }

    // ================= Phase 1: Q = edge_f @ W1c (2 passes of N=256) ========
    {
        const int wnl = warp * 32;
        auto cpB1 = [&](int np, int s) {
            char* dB = sStr + (s & 1) * 16384;
#pragma unroll
            for (int t = 0; t < 4; ++t) {
                int idx = tid + t * 256;
                int n = idx >> 2, j = idx & 3;
                cp_async16(dB + n * 64 + swz(n, j),
                           g_w1c + (size_t)(np * 256 + n) * 128 + s * 32 + j * 8);
            }
        };
#pragma unroll
        for (int np = 0; np < 2; ++np) {
            float cf1[4][4][4] = {};
            cpB1(np, 0); cp_commit();
            cpB1(np, 1); cp_commit();
#pragma unroll
            for (int s = 0; s < 4; ++s) {
                if (s + 1 < 4) cp_wait1(); else cp_wait0();
                __syncthreads();
                const uint32_t fA = uEf + s * 4096;
                const uint32_t fB = uStr + (s & 1) * 16384;
#pragma unroll
                for (int g = 0; g < 2; ++g) {
                    uint32_t av[4][4], bv[2][4];
#pragma unroll
                    for (int ma = 0; ma < 4; ++ma) {
                        const int row = ma * 16 + arow;
                        ldsm4(av[ma], fA + row * 64 + swz(row, 2 * g + acs));
                    }
#pragma unroll
                    for (int p = 0; p < 2; ++p) {
                        const int n = wnl + p * 16 + brow;
                        ldsm4(bv[p], fB + n * 64 + swz(n, 2 * g + bcs));
                    }
#pragma unroll
                    for (int ma = 0; ma < 4; ++ma)
#pragma unroll
                        for (int na = 0; na < 4; ++na)
                            mma16816(cf1[ma][na], av[ma][0], av[ma][1], av[ma][2], av[ma][3],
                                     bv[na >> 1][(na & 1) * 2], bv[na >> 1][(na & 1) * 2 + 1]);
                }
                __syncthreads();
                if (s + 2 < 4) { cpB1(np, s + 2); cp_commit(); }
            }
#pragma unroll
            for (int ma = 0; ma < 4; ++ma) {
                const int row0 = ma * 16 + r;
#pragma unroll
                for (int na = 0; na < 4; ++na) {
                    const int nloc = np * 256 + wnl + na * 8 + 2 * c;
                    stsC(sQ, row0,     nloc, cf1[ma][na][0], cf1[ma][na][1]);
                    stsC(sQ, row0 + 8, nloc, cf1[ma][na][2], cf1[ma][na][3]);
                }
            }
            __syncthreads();
        }
    }

    // ================= Phase 2: W2 + W3 (single barrier per stage) ==========
    {
        float* sB2 = (float*)sEf;            // 256 f32
        float* sW3 = (float*)(sEf + 1024);   // 256 f32
        float* psum = (float*)(sEf + 2048);  // 64 x 8 f32
        sB2[tid] = __ldg(b2 + tid);
        sW3[tid] = __ldg(W3 + tid);

        const int row = tid >> 2, j = tid & 3;
        const int e = min(bm + row, M - 1);
        const __half* paP = g_pab + (size_t)g_src[e] * 1024;
        const __half* pbP = g_pab + (size_t)g_dst[e] * 1024 + 512;
        char* qaddrBase = sQ + row * 64 + swz(row, j);
        const int wnl = warp * 32;

        uint4 ra, rb;
        auto ldgA = [&](int s) {
            ra = __ldg((const uint4*)(paP + s * 32 + j * 8));
            rb = __ldg((const uint4*)(pbP + s * 32 + j * 8));
        };
        auto finA = [&](int s) {
            uint4 q4 = *(uint4*)(qaddrBase + s * 4096);
            const half2* qh = (const half2*)&q4;
            const half2* ha = (const half2*)&ra;
            const half2* hb = (const half2*)&rb;
            half2 v[4];
            const half2 z = __float2half2_rn(0.f);
#pragma unroll
            for (int i = 0; i < 4; ++i)
                v[i] = __hmax2(__hadd2(__hadd2(qh[i], ha[i]), hb[i]), z);
            *(uint4*)(qaddrBase + s * 4096) = *(uint4*)v;
        };
        // per-warp B loader: warp loads ONLY its own 32 rows (== its read set)
        auto cpB2w = [&](int s) {
            char* dB = sStr + (s & 1) * 16384;
#pragma unroll
            for (int t = 0; t < 4; ++t) {
                int idx = lane + t * 32;            // 0..127
                int nl = idx >> 2, j2 = idx & 3;    // nl 0..31
                int n = wnl + nl;
                cp_async16(dB + n * 64 + swz(n, j2),
                           g_w2t + (size_t)n * 512 + s * 32 + j2 * 8);
            }
        };

        float cf[4][4][4] = {};

        ldgA(0);
        cpB2w(0); cp_commit();
        cpB2w(1); cp_commit();
        finA(0);
        ldgA(1);

#pragma unroll 1
        for (int s = 0; s < 16; ++s) {
            if (s + 1 < 16) cp_wait1(); else cp_wait0();
            __syncthreads();        // finA(s) from all warps + own B(s) ready
            const uint32_t fA = uQ + s * 4096;
            const uint32_t fB = uStr + (s & 1) * 16384;
#pragma unroll
            for (int g = 0; g < 2; ++g) {
                uint32_t av[4][4], bv[2][4];
#pragma unroll
                for (int ma = 0; ma < 4; ++ma) {
                    const int rw = ma * 16 + arow;
                    ldsm4(av[ma], fA + rw * 64 + swz(rw, 2 * g + acs));
                }
#pragma unroll
                for (int p = 0; p < 2; ++p) {
                    const int n = wnl + p * 16 + brow;
                    ldsm4(bv[p], fB + n * 64 + swz(n, 2 * g + bcs));
                }
#pragma unroll
                for (int ma = 0; ma < 4; ++ma)
#pragma unroll
                    for (int na = 0; na < 4; ++na)
                        mma16816(cf[ma][na], av[ma][0], av[ma][1], av[ma][2], av[ma][3],
                                 bv[na >> 1][(na & 1) * 2], bv[na >> 1][(na & 1) * 2 + 1]);
            }
            if (s + 2 < 16) { cpB2w(s + 2); cp_commit(); }
            if (s + 1 < 16) {
                finA(s + 1);
                if (s + 2 < 16) ldgA(s + 2);
            }
        }

        float2 bias2[4], w3v[4];
#pragma unroll
        for (int na = 0; na < 4; ++na) {
            bias2[na] = *(const float2*)&sB2[wnl + na * 8 + 2 * c];
            w3v[na]   = *(const float2*)&sW3[wnl + na * 8 + 2 * c];
        }
#pragma unroll
        for (int ma = 0; ma < 4; ++ma) {
            float p0 = 0.f, p1 = 0.f;
#pragma unroll
            for (int na = 0; na < 4; ++na) {
                p0 += fmaxf(cf[ma][na][0] + bias2[na].x, 0.f) * w3v[na].x
                    + fmaxf(cf[ma][na][1] + bias2[na].y, 0.f) * w3v[na].y;
                p1 += fmaxf(cf[ma][na][2] + bias2[na].x, 0.f) * w3v[na].x
                    + fmaxf(cf[ma][na][3] + bias2[na].y, 0.f) * w3v[na].y;
            }
            p0 += __shfl_xor_sync(0xffffffffu, p0, 1);
            p0 += __shfl_xor_sync(0xffffffffu, p0, 2);
            p1 += __shfl_xor_sync(0xffffffffu, p1, 1);
            p1 += __shfl_xor_sync(0xffffffffu, p1, 2);
            if (c == 0) {
                const int rl = ma * 16 + r;
                psum[rl * 8 + warp] = p0;
                psum[(rl + 8) * 8 + warp] = p1;
            }
        }
        __syncthreads();
        if (tid < 64) {
            const int gm = bm + tid;
            if (gm < M) {
                float s = 0.f;
#pragma unroll
                for (int w = 0; w < 8; ++w) s += psum[tid * 8 + w];
                outv[gm] = s + __ldg(b3);
            }
        }
    }
}

// ============================================================================
extern "C" void kernel_launch(void* const* d_in, const int* in_sizes, int n_in,
                              void* d_out, int out_size)
{
    const float* x     = (const float*)d_in[0];
    const void*  eidx  = d_in[1];
    const float* eattr = (const float*)d_in[2];
    const float* Wn    = (const float*)d_in[3];
    const float* bnode = (const float*)d_in[4];
    const float* We    = (const float*)d_in[5];
    const float* be    = (const float*)d_in[6];
    const float* W1    = (const float*)d_in[7];
    const float* b1    = (const float*)d_in[8];
    const float* W2    = (const float*)d_in[9];
    const float* b2    = (const float*)d_in[10];
    const float* W3    = (const float*)d_in[11];
    const float* b3    = (const float*)d_in[12];
    float* out = (float*)d_out;

    __half *p_node, *p_pab, *p_xt, *p_wnt, *p_w1ab;
    float* p_b1024;
    cudaGetSymbolAddress((void**)&p_node, g_node_f);
    cudaGetSymbolAddress((void**)&p_pab, g_pab);
    cudaGetSymbolAddress((void**)&p_xt, g_xt);
    cudaGetSymbolAddress((void**)&p_wnt, g_wnt);
    cudaGetSymbolAddress((void**)&p_w1ab, g_w1ab);
    cudaGetSymbolAddress((void**)&p_b1024, g_bias1024);

    // launches: 0 front (idx+preps), 1 node_enc, 2 pab, 3 fq
    front_kernel<<<FB_B1, 256>>>(eidx, x, Wn, We, W1, W2, b1);

    // node encoder [50000,128]
    cudaFuncSetAttribute(mm_kernel<128, 128, true>,
                         cudaFuncAttributeMaxDynamicSharedMemorySize, MM_SMEM);
    mm_kernel<128, 128, true><<<dim3(1, (kNodes + 127) / 128), 256, MM_SMEM>>>(
        p_xt, p_wnt, bnode, p_node, kNodes);

    // Pab = node_f @ [W1a|W1b] + [b1|0]   [50000,1024]
    cudaFuncSetAttribute(mm_kernel<128, 1024, false>,
                         cudaFuncAttributeMaxDynamicSharedMemorySize, MM_SMEM);
    mm_kernel<128, 1024, false><<<dim3(8, (kNodes + 127) / 128), 256, MM_SMEM>>>(
        p_node, p_w1ab, p_b1024, p_pab, kNodes);

    // fused edge pipeline
    cudaFuncSetAttribute(fq_kernel,
                         cudaFuncAttributeMaxDynamicSharedMemorySize, FQ_SMEM);
    fq_kernel<<<(kEdges + 63) / 64, 256, FQ_SMEM>>>(eattr, be, b2, W3, b3, out, kEdges);
}

// round 17
// speedup vs baseline: 1.5521x; 1.0462x over previous
#include <cuda_runtime.h>
#include <cuda_fp16.h>
#include <cstdint>

namespace {
constexpr int kNodes = 50000;
constexpr int kEdges = 500000;
constexpr int MM_SMEM = 50176;    // mm_kernel: sA 3*8K | sB 3*8K | bias 512B
// fq_kernel: sQ 16*4K=64K | sEf 4*4K=16K | stream 2*16K=32K  => 114688
constexpr int FQ_SMEM = 114688;
// front_kernel block ranges
constexpr int FB_CONV = (kEdges + 255) / 256;      // 1954
constexpr int FB_X    = FB_CONV + 12500;           // x -> g_xt
constexpr int FB_WN   = FB_X + 64;
constexpr int FB_WE   = FB_WN + 32;
constexpr int FB_W2   = FB_WE + 512;
constexpr int FB_W1AB = FB_W2 + 512;
constexpr int FB_W1C  = FB_W1AB + 256;
constexpr int FB_B1   = FB_W1C + 4;
}

// ============================================================================
// Static scratch. All half matrices PLAIN K-major (ldmatrix defines fragment
// distribution).
// ============================================================================
__device__ __half g_node_f[(size_t)kNodes * 128];
__device__ __half g_pab[(size_t)kNodes * 1024];   // [node_f@W1a + b1 | node_f@W1b]
__device__ __half g_xt[(size_t)kNodes * 128];
__device__ __half g_wnt[128 * 128];
__device__ __half g_wet[128 * 64];
__device__ __half g_w1ab[1024 * 128];
__device__ __half g_w1c[512 * 128];
__device__ __half g_w2t[256 * 512];
__device__ float  g_bias1024[1024];
__device__ int    g_src[kEdges];
__device__ int    g_dst[kEdges];

// ============================================================================
// Helpers
// ============================================================================
__device__ __forceinline__ uint32_t smem_u32(const void* p) {
    uint32_t a;
    asm("{ .reg .u64 t; cvta.to.shared.u64 t, %1; cvt.u32.u64 %0, t; }" : "=r"(a) : "l"(p));
    return a;
}
__device__ __forceinline__ void cp_async16(void* smem, const void* gmem) {
    uint32_t s;
    asm("{ .reg .u64 t; cvta.to.shared.u64 t, %1; cvt.u32.u64 %0, t; }" : "=r"(s) : "l"(smem));
    asm volatile("cp.async.cg.shared.global [%0], [%1], 16;\n" :: "r"(s), "l"(gmem));
}
__device__ __forceinline__ void cp_commit() { asm volatile("cp.async.commit_group;\n"); }
__device__ __forceinline__ void cp_wait0()  { asm volatile("cp.async.wait_group 0;\n" ::: "memory"); }
__device__ __forceinline__ void cp_wait1()  { asm volatile("cp.async.wait_group 1;\n" ::: "memory"); }

__device__ __forceinline__ void mma16816(float* cc, uint32_t a0, uint32_t a1,
                                         uint32_t a2, uint32_t a3,
                                         uint32_t b0, uint32_t b1) {
    asm volatile(
        "mma.sync.aligned.m16n8k16.row.col.f32.f16.f16.f32 "
        "{%0,%1,%2,%3}, {%4,%5,%6,%7}, {%8,%9}, {%0,%1,%2,%3};"
        : "+f"(cc[0]), "+f"(cc[1]), "+f"(cc[2]), "+f"(cc[3])
        : "r"(a0), "r"(a1), "r"(a2), "r"(a3), "r"(b0), "r"(b1));
}
__device__ __forceinline__ void ldsm4(uint32_t* r, uint32_t addr) {
    asm volatile("ldmatrix.sync.aligned.m8n8.x4.shared.b16 {%0,%1,%2,%3}, [%4];"
                 : "=r"(r[0]), "=r"(r[1]), "=r"(r[2]), "=r"(r[3]) : "r"(addr));
}
// smem chunk swizzle: 16B chunk j of row stored at j ^ ((row>>1)&3)
__device__ __forceinline__ int swz(int row, int j) {
    return (j ^ ((row >> 1) & 3)) << 4;
}

// ============================================================================
// Front kernel: index conversion + all weight/activation preps, ONE launch.
// ============================================================================
__global__ void front_kernel(const void* __restrict__ idx, const float* __restrict__ x,
                             const float* __restrict__ Wn, const float* __restrict__ We,
                             const float* __restrict__ W1, const float* __restrict__ W2,
                             const float* __restrict__ b1) {
    const int b = blockIdx.x;
    const int t = threadIdx.x;
    if (b < FB_CONV) {
        __shared__ int s_is64;
        const long long v = ((const long long*)idx)[t];
        int bad = (v < 0) || (v >= kNodes);
        int cnt = __syncthreads_count(bad);
        if (t == 0) s_is64 = (cnt == 0);
        __syncthreads();
        const int is64 = s_is64;
        const int i = b * 256 + t;
        if (i < kEdges) {
            int s, d;
            if (is64) {
                const long long* p = (const long long*)idx;
                s = (int)p[i]; d = (int)p[kEdges + i];
            } else {
                const int* p = (const int*)idx;
                s = p[i]; d = p[kEdges + i];
            }
            g_src[i] = s; g_dst[i] = d;
        }
    } else if (b < FB_X) {
        int i2 = (b - FB_CONV) * 256 + t;    // pair index, plain copy
        float2 v = ((const float2*)x)[i2];
        __half2 h; h.x = __float2half_rn(v.x); h.y = __float2half_rn(v.y);
        ((__half2*)g_xt)[i2] = h;
    } else if (b < FB_WN) {
        int i = (b - FB_X) * 256 + t;        // K=128,N=128
        int k = i >> 7, n = i & 127;
        g_wnt[n * 128 + k] = __float2half_rn(Wn[i]);
    } else if (b < FB_WE) {
        int i = (b - FB_WN) * 256 + t;       // K=64,N=128
        int k = i >> 7, n = i & 127;
        g_wet[n * 64 + k] = __float2half_rn(We[i]);
    } else if (b < FB_W2) {
        int i = (b - FB_WE) * 256 + t;       // K=512,N=256
        int k = i >> 8, n = i & 255;
        g_w2t[(size_t)n * 512 + k] = __float2half_rn(W2[i]);
    } else if (b < FB_W1AB) {
        int i = (b - FB_W2) * 256 + t;       // n = i>>7 (0..1023), k = i&127
        int n = i >> 7, k = i & 127;
        int srcRow = (n < 512) ? k : (128 + k);
        int srcCol = (n < 512) ? n : (n - 512);
        g_w1ab[(size_t)n * 128 + k] = __float2half_rn(W1[(size_t)srcRow * 512 + srcCol]);
    } else if (b < FB_W1C) {
        int i = (b - FB_W1AB) * 256 + t;     // n = i>>7 (0..511), k = i&127
        int n = i >> 7, k = i & 127;
        g_w1c[(size_t)n * 128 + k] = __float2half_rn(W1[(size_t)(256 + k) * 512 + n]);
    } else {
        int i = (b - FB_W1C) * 256 + t;
        if (i < 1024) g_bias1024[i] = (i < 512) ? b1[i] : 0.f;
    }
}

// ============================================================================
// FP16 mma GEMM (node-side): C[M,N] = act(A@Bt^T + bias), plain fp16 store.
// ============================================================================
template <int K, int N, bool RELU>
__global__ __launch_bounds__(256, 2)
void mm_kernel(const __half* __restrict__ A, const __half* __restrict__ Bt,
               const float* __restrict__ bias, __half* __restrict__ Cmat, int M)
{
    constexpr int NS = K / 32;
    extern __shared__ char smc[];
    char*  sAc   = smc;
    char*  sBc   = smc + 24576;
    float* sBias = (float*)(smc + 49152);

    const int tid  = threadIdx.x;
    const int lane = tid & 31;
    const int warp = tid >> 5;
    const int r    = lane >> 2;
    const int c    = lane & 3;
    const int rr   = lane & 7;
    const int sub  = lane >> 3;
    const int arow = rr + ((sub & 1) << 3);
    const int acs  = sub >> 1;
    const int brow = rr + ((sub >> 1) << 3);
    const int bcs  = sub & 1;
    const int wm   = (warp >> 2) * 64;
    const int wnl  = (warp & 3) * 32;
    const int bn   = blockIdx.x * 128;
    const int bm   = blockIdx.y * 128;
    const uint32_t uA = smem_u32(sAc);
    const uint32_t uB = smem_u32(sBc);

    if (tid < 128) sBias[tid] = bias ? __ldg(bias + bn + tid) : 0.f;
    __syncthreads();

    auto load_stage = [&](int s) {
        const int buf = s % 3;
        const int k0 = s * 32;
        char* dA = sAc + buf * 8192;
        char* dB = sBc + buf * 8192;
#pragma unroll
        for (int t = 0; t < 2; ++t) {
            int idx = tid + t * 256;
            int row = idx >> 2, j = idx & 3;
            cp_async16(dA + row * 64 + swz(row, j),
                       A + (size_t)min(bm + row, M - 1) * K + k0 + j * 8);
        }
#pragma unroll
        for (int t = 0; t < 2; ++t) {
            int idx = tid + t * 256;
            int n = idx >> 2, j = idx & 3;
            cp_async16(dB + n * 64 + swz(n, j),
                       Bt + (size_t)(bn + n) * K + k0 + j * 8);
        }
    };

    float cf[4][4][4] = {};
    load_stage(0); cp_commit();
    if (NS > 1) { load_stage(1); cp_commit(); }

    for (int s = 0; s < NS; ++s) {
        if (s + 1 < NS) cp_wait1(); else cp_wait0();
        __syncthreads();
        if (s + 2 < NS) { load_stage(s + 2); cp_commit(); }

        const uint32_t fA = uA + (s % 3) * 8192;
        const uint32_t fB = uB + (s % 3) * 8192;
#pragma unroll
        for (int g = 0; g < 2; ++g) {
            uint32_t av[4][4], bv[2][4];
#pragma unroll
            for (int ma = 0; ma < 4; ++ma) {
                const int row = wm + ma * 16 + arow;
                ldsm4(av[ma], fA + row * 64 + swz(row, 2 * g + acs));
            }
#pragma unroll
            for (int p = 0; p < 2; ++p) {
                const int n = wnl + p * 16 + brow;
                ldsm4(bv[p], fB + n * 64 + swz(n, 2 * g + bcs));
            }
#pragma unroll
            for (int ma = 0; ma < 4; ++ma)
#pragma unroll
                for (int na = 0; na < 4; ++na)
                    mma16816(cf[ma][na], av[ma][0], av[ma][1], av[ma][2], av[ma][3],
                             bv[na >> 1][(na & 1) * 2], bv[na >> 1][(na & 1) * 2 + 1]);
        }
    }
    __syncthreads();

    float2 bias2[4];
#pragma unroll
    for (int na = 0; na < 4; ++na)
        bias2[na] = *(const float2*)&sBias[wnl + na * 8 + 2 * c];

#pragma unroll
    for (int ma = 0; ma < 4; ++ma) {
        const int row0 = bm + wm + ma * 16 + r;
        const int row1 = row0 + 8;
#pragma unroll
        for (int na = 0; na < 4; ++na) {
            const int pcol = bn + wnl + na * 8 + 2 * c;
            float v0 = cf[ma][na][0] + bias2[na].x;
            float v1 = cf[ma][na][1] + bias2[na].y;
            float v2 = cf[ma][na][2] + bias2[na].x;
            float v3 = cf[ma][na][3] + bias2[na].y;
            if (RELU) {
                v0 = fmaxf(v0, 0.f); v1 = fmaxf(v1, 0.f);
                v2 = fmaxf(v2, 0.f); v3 = fmaxf(v3, 0.f);
            }
            if (row0 < M) {
                __half2 h; h.x = __float2half_rn(v0); h.y = __float2half_rn(v1);
                *(__half2*)(Cmat + (size_t)row0 * N + pcol) = h;
            }
            if (row1 < M) {
                __half2 h; h.x = __float2half_rn(v2); h.y = __float2half_rn(v3);
                *(__half2*)(Cmat + (size_t)row1 * N + pcol) = h;
            }
        }
    }
}

// ============================================================================
// Fused edge kernel (per-CTA 64 edges).
//  P0: edge_f = relu(eattr@We+be)  -> sEf            (CTA barriers, one-shot)
//  P1: Q = edge_f @ W1c            -> sQ   BARRIER-FREE: per-warp B regions
//      (wnl..wnl+31), warp-sliced sQ columns; 8 global stages, continuous
//      double-buffer prefetch across both N-passes.
//  P2: A = relu(Pa[src]+Pb[dst]+Q) in place; out = relu(A@W2+b2).W3 + b3
//      (one barrier per stage; entry barrier orders P1 stsC vs finA/sB2).
// ============================================================================
__global__ __launch_bounds__(256, 2)
void fq_kernel(const float* __restrict__ eattr,
               const float* __restrict__ be, const float* __restrict__ b2,
               const float* __restrict__ W3, const float* __restrict__ b3,
               float* __restrict__ outv, int M)
{
    extern __shared__ char smc[];
    char* sQ  = smc;            // 16 x 4096
    char* sEf = smc + 65536;    // 4 x 4096
    char* sStr = smc + 81920;   // 32768 stream region

    const int tid  = threadIdx.x;
    const int lane = tid & 31;
    const int warp = tid >> 5;
    const int r    = lane >> 2;
    const int c    = lane & 3;
    const int rr   = lane & 7;
    const int sub  = lane >> 3;
    const int arow = rr + ((sub & 1) << 3);
    const int acs  = sub >> 1;
    const int brow = rr + ((sub >> 1) << 3);
    const int bcs  = sub & 1;
    const int bm   = blockIdx.x * 64;
    const uint32_t uQ  = smem_u32(sQ);
    const uint32_t uEf = smem_u32(sEf);
    const uint32_t uStr = smem_u32(sStr);

    auto stsC = [&](char* tiles, int row, int nloc, float v0, float v1) {
        const int stage = nloc >> 5;
        const int byte = (nloc & 31) * 2;
        const int j = byte >> 4;
        __half2 h; h.x = __float2half_rn(v0); h.y = __float2half_rn(v1);
        *(__half2*)(tiles + stage * 4096 + row * 64 + swz(row, j) + (byte & 15)) = h;
    };

    // ================= Phase 0: edge encoder =================
    {
        char* sA0 = sStr;             // 2 x 4096
        char* sB0 = sStr + 8192;      // 2 x 8192
        float* sBe = (float*)(sStr + 24576);   // 128 f32

        if (tid < 128) sBe[tid] = __ldg(be + tid);
#pragma unroll
        for (int t = 0; t < 4; ++t) {
            int idx = tid + t * 256;
            int stage = idx >> 9, rem = idx & 511;
            int n = rem >> 2, j = rem & 3;
            cp_async16(sB0 + stage * 8192 + n * 64 + swz(n, j),
                       g_wet + (size_t)n * 64 + stage * 32 + j * 8);
        }
        cp_commit();
        {
            const int row = tid >> 2, seg = tid & 3;
            const int e = min(bm + row, M - 1);
            const float* es = eattr + (size_t)e * 64 + seg * 16;
            __half arr[16];
#pragma unroll
            for (int q4 = 0; q4 < 4; ++q4) {
                float4 v = __ldg((const float4*)(es + q4 * 4));
                arr[q4 * 4]     = __float2half_rn(v.x);
                arr[q4 * 4 + 1] = __float2half_rn(v.y);
                arr[q4 * 4 + 2] = __float2half_rn(v.z);
                arr[q4 * 4 + 3] = __float2half_rn(v.w);
            }
            const int stage = seg >> 1, jb = (seg & 1) * 2;
            char* base = sA0 + stage * 4096 + row * 64;
            *(uint4*)(base + swz(row, jb))     = *(uint4*)arr;
            *(uint4*)(base + swz(row, jb + 1)) = *(uint4*)(arr + 8);
        }
        cp_wait0();
        __syncthreads();

        const int wm0 = (warp >> 2) * 32;
        const int wnl0 = (warp & 3) * 32;
        const uint32_t uA0 = uStr;
        const uint32_t uB0 = uStr + 8192;
        float cf0[2][4][4] = {};
#pragma unroll
        for (int s0 = 0; s0 < 2; ++s0) {
            const uint32_t fA = uA0 + s0 * 4096;
            const uint32_t fB = uB0 + s0 * 8192;
#pragma unroll
            for (int g = 0; g < 2; ++g) {
                uint32_t av[2][4], bv[2][4];
#pragma unroll
                for (int ma = 0; ma < 2; ++ma) {
                    const int row = wm0 + ma * 16 + arow;
                    ldsm4(av[ma], fA + row * 64 + swz(row, 2 * g + acs));
                }
#pragma unroll
                for (int p = 0; p < 2; ++p) {
                    const int n = wnl0 + p * 16 + brow;
                    ldsm4(bv[p], fB + n * 64 + swz(n, 2 * g + bcs));
                }
#pragma unroll
                for (int ma = 0; ma < 2; ++ma)
#pragma unroll
                    for (int na = 0; na < 4; ++na)
                        mma16816(cf0[ma][na], av[ma][0], av[ma][1], av[ma][2], av[ma][3],
                                 bv[na >> 1][(na & 1) * 2], bv[na >> 1][(na & 1) * 2 + 1]);
            }
        }
        __syncthreads();
#pragma unroll
        for (int ma = 0; ma < 2; ++ma) {
            const int row0 = wm0 + ma * 16 + r;
#pragma unroll
            for (int na = 0; na < 4; ++na) {
                const int nloc = wnl0 + na * 8 + 2 * c;
                float b0 = sBe[nloc], b1v = sBe[nloc + 1];
                stsC(sEf, row0,     nloc, fmaxf(cf0[ma][na][0] + b0, 0.f),
                                          fmaxf(cf0[ma][na][1] + b1v, 0.f));
                stsC(sEf, row0 + 8, nloc, fmaxf(cf0[ma][na][2] + b0, 0.f),
                                          fmaxf(cf0[ma][na][3] + b1v, 0.f));
            }
        }
        __syncthreads();   // sEf visible to all; stream region free for P1
    }

    // ====== Phase 1: Q = edge_f @ W1c — BARRIER-FREE, 8 global stages =======
    // gs = np*4 + s; pass np covers W1c rows [np*256, np*256+256), Q cols same.
    // Warp loads ONLY its own B rows (wnl..wnl+31) => all hazards warp-private.
    {
        const int wnl = warp * 32;
        auto cpB1w = [&](int gs) {
            char* dB = sStr + (gs & 1) * 16384;
            const int np2 = gs >> 2, s2 = gs & 3;
#pragma unroll
            for (int t = 0; t < 4; ++t) {
                int idx = lane + t * 32;
                int nl = idx >> 2, j2 = idx & 3;
                int n = wnl + nl;
                cp_async16(dB + n * 64 + swz(n, j2),
                           g_w1c + (size_t)(np2 * 256 + n) * 128 + s2 * 32 + j2 * 8);
            }
        };

        cpB1w(0); cp_commit();
        cpB1w(1); cp_commit();

#pragma unroll
        for (int np = 0; np < 2; ++np) {
            float cf1[4][4][4] = {};
#pragma unroll
            for (int s = 0; s < 4; ++s) {
                const int gs = np * 4 + s;
                if (gs + 1 < 8) cp_wait1(); else cp_wait0();
                const uint32_t fA = uEf + s * 4096;
                const uint32_t fB = uStr + (gs & 1) * 16384;
#pragma unroll
                for (int g = 0; g < 2; ++g) {
                    uint32_t av[4][4], bv[2][4];
#pragma unroll
                    for (int ma = 0; ma < 4; ++ma) {
                        const int row = ma * 16 + arow;
                        ldsm4(av[ma], fA + row * 64 + swz(row, 2 * g + acs));
                    }
#pragma unroll
                    for (int p = 0; p < 2; ++p) {
                        const int n = wnl + p * 16 + brow;
                        ldsm4(bv[p], fB + n * 64 + swz(n, 2 * g + bcs));
                    }
#pragma unroll
                    for (int ma = 0; ma < 4; ++ma)
#pragma unroll
                        for (int na = 0; na < 4; ++na)
                            mma16816(cf1[ma][na], av[ma][0], av[ma][1], av[ma][2], av[ma][3],
                                     bv[na >> 1][(na & 1) * 2], bv[na >> 1][(na & 1) * 2 + 1]);
                }
                if (gs + 2 < 8) { cpB1w(gs + 2); cp_commit(); }
            }
            // epilogue: write Q pass (warp-sliced columns; no barrier needed)
#pragma unroll
            for (int ma = 0; ma < 4; ++ma) {
                const int row0 = ma * 16 + r;
#pragma unroll
                for (int na = 0; na < 4; ++na) {
                    const int nloc = np * 256 + wnl + na * 8 + 2 * c;
                    stsC(sQ, row0,     nloc, cf1[ma][na][0], cf1[ma][na][1]);
                    stsC(sQ, row0 + 8, nloc, cf1[ma][na][2], cf1[ma][na][3]);
                }
            }
        }
    }

    // ================= Phase 2: W2 + W3 (single barrier per stage) ==========
    {
        __syncthreads();   // REQUIRED: P1 stsC(sQ) -> cross-warp finA reads;
                           // and sB2/sW3 overlay sEf which P1 read as A.
        float* sB2 = (float*)sEf;            // 256 f32
        float* sW3 = (float*)(sEf + 1024);   // 256 f32
        float* psum = (float*)(sEf + 2048);  // 64 x 8 f32
        sB2[tid] = __ldg(b2 + tid);
        sW3[tid] = __ldg(W3 + tid);

        const int row = tid >> 2, j = tid & 3;
        const int e = min(bm + row, M - 1);
        const __half* paP = g_pab + (size_t)g_src[e] * 1024;
        const __half* pbP = g_pab + (size_t)g_dst[e] * 1024 + 512;
        char* qaddrBase = sQ + row * 64 + swz(row, j);
        const int wnl = warp * 32;

        uint4 ra, rb;
        auto ldgA = [&](int s) {
            ra = __ldg((const uint4*)(paP + s * 32 + j * 8));
            rb = __ldg((const uint4*)(pbP + s * 32 + j * 8));
        };
        auto finA = [&](int s) {
            uint4 q4 = *(uint4*)(qaddrBase + s * 4096);
            const half2* qh = (const half2*)&q4;
            const half2* ha = (const half2*)&ra;
            const half2* hb = (const half2*)&rb;
            half2 v[4];
            const half2 z = __float2half2_rn(0.f);
#pragma unroll
            for (int i = 0; i < 4; ++i)
                v[i] = __hmax2(__hadd2(__hadd2(qh[i], ha[i]), hb[i]), z);
            *(uint4*)(qaddrBase + s * 4096) = *(uint4*)v;
        };
        auto cpB2w = [&](int s) {
            char* dB = sStr + (s & 1) * 16384;
#pragma unroll
            for (int t = 0; t < 4; ++t) {
                int idx = lane + t * 32;
                int nl = idx >> 2, j2 = idx & 3;
                int n = wnl + nl;
                cp_async16(dB + n * 64 + swz(n, j2),
                           g_w2t + (size_t)n * 512 + s * 32 + j2 * 8);
            }
        };

        float cf[4][4][4] = {};

        ldgA(0);
        cpB2w(0); cp_commit();
        cpB2w(1); cp_commit();
        finA(0);
        ldgA(1);

#pragma unroll 1
        for (int s = 0; s < 16; ++s) {
            if (s + 1 < 16) cp_wait1(); else cp_wait0();
            __syncthreads();        // finA(s) from all warps + own B(s) ready
            const uint32_t fA = uQ + s * 4096;
            const uint32_t fB = uStr + (s & 1) * 16384;
#pragma unroll
            for (int g = 0; g < 2; ++g) {
                uint32_t av[4][4], bv[2][4];
#pragma unroll
                for (int ma = 0; ma < 4; ++ma) {
                    const int rw = ma * 16 + arow;
                    ldsm4(av[ma], fA + rw * 64 + swz(rw, 2 * g + acs));
                }
#pragma unroll
                for (int p = 0; p < 2; ++p) {
                    const int n = wnl + p * 16 + brow;
                    ldsm4(bv[p], fB + n * 64 + swz(n, 2 * g + bcs));
                }
#pragma unroll
                for (int ma = 0; ma < 4; ++ma)
#pragma unroll
                    for (int na = 0; na < 4; ++na)
                        mma16816(cf[ma][na], av[ma][0], av[ma][1], av[ma][2], av[ma][3],
                                 bv[na >> 1][(na & 1) * 2], bv[na >> 1][(na & 1) * 2 + 1]);
            }
            if (s + 2 < 16) { cpB2w(s + 2); cp_commit(); }
            if (s + 1 < 16) {
                finA(s + 1);
                if (s + 2 < 16) ldgA(s + 2);
            }
        }

        float2 bias2[4], w3v[4];
#pragma unroll
        for (int na = 0; na < 4; ++na) {
            bias2[na] = *(const float2*)&sB2[wnl + na * 8 + 2 * c];
            w3v[na]   = *(const float2*)&sW3[wnl + na * 8 + 2 * c];
        }
#pragma unroll
        for (int ma = 0; ma < 4; ++ma) {
            float p0 = 0.f, p1 = 0.f;
#pragma unroll
            for (int na = 0; na < 4; ++na) {
                p0 += fmaxf(cf[ma][na][0] + bias2[na].x, 0.f) * w3v[na].x
                    + fmaxf(cf[ma][na][1] + bias2[na].y, 0.f) * w3v[na].y;
                p1 += fmaxf(cf[ma][na][2] + bias2[na].x, 0.f) * w3v[na].x
                    + fmaxf(cf[ma][na][3] + bias2[na].y, 0.f) * w3v[na].y;
            }
            p0 += __shfl_xor_sync(0xffffffffu, p0, 1);
            p0 += __shfl_xor_sync(0xffffffffu, p0, 2);
            p1 += __shfl_xor_sync(0xffffffffu, p1, 1);
            p1 += __shfl_xor_sync(0xffffffffu, p1, 2);
            if (c == 0) {
                const int rl = ma * 16 + r;
                psum[rl * 8 + warp] = p0;
                psum[(rl + 8) * 8 + warp] = p1;
            }
        }
        __syncthreads();
        if (tid < 64) {
            const int gm = bm + tid;
            if (gm < M) {
                float s = 0.f;
#pragma unroll
                for (int w = 0; w < 8; ++w) s += psum[tid * 8 + w];
                outv[gm] = s + __ldg(b3);
            }
        }
    }
}

// ============================================================================
extern "C" void kernel_launch(void* const* d_in, const int* in_sizes, int n_in,
                              void* d_out, int out_size)
{
    const float* x     = (const float*)d_in[0];
    const void*  eidx  = d_in[1];
    const float* eattr = (const float*)d_in[2];
    const float* Wn    = (const float*)d_in[3];
    const float* bnode = (const float*)d_in[4];
    const float* We    = (const float*)d_in[5];
    const float* be    = (const float*)d_in[6];
    const float* W1    = (const float*)d_in[7];
    const float* b1    = (const float*)d_in[8];
    const float* W2    = (const float*)d_in[9];
    const float* b2    = (const float*)d_in[10];
    const float* W3    = (const float*)d_in[11];
    const float* b3    = (const float*)d_in[12];
    float* out = (float*)d_out;

    __half *p_node, *p_pab, *p_xt, *p_wnt, *p_w1ab;
    float* p_b1024;
    cudaGetSymbolAddress((void**)&p_node, g_node_f);
    cudaGetSymbolAddress((void**)&p_pab, g_pab);
    cudaGetSymbolAddress((void**)&p_xt, g_xt);
    cudaGetSymbolAddress((void**)&p_wnt, g_wnt);
    cudaGetSymbolAddress((void**)&p_w1ab, g_w1ab);
    cudaGetSymbolAddress((void**)&p_b1024, g_bias1024);

    // launches: 0 front (idx+preps), 1 node_enc, 2 pab, 3 fq
    front_kernel<<<FB_B1, 256>>>(eidx, x, Wn, We, W1, W2, b1);

    // node encoder [50000,128]
    cudaFuncSetAttribute(mm_kernel<128, 128, true>,
                         cudaFuncAttributeMaxDynamicSharedMemorySize, MM_SMEM);
    mm_kernel<128, 128, true><<<dim3(1, (kNodes + 127) / 128), 256, MM_SMEM>>>(
        p_xt, p_wnt, bnode, p_node, kNodes);

    // Pab = node_f @ [W1a|W1b] + [b1|0]   [50000,1024]
    cudaFuncSetAttribute(mm_kernel<128, 1024, false>,
                         cudaFuncAttributeMaxDynamicSharedMemorySize, MM_SMEM);
    mm_kernel<128, 1024, false><<<dim3(8, (kNodes + 127) / 128), 256, MM_SMEM>>>(
        p_node, p_w1ab, p_b1024, p_pab, kNodes);

    // fused edge pipeline
    cudaFuncSetAttribute(fq_kernel,
                         cudaFuncAttributeMaxDynamicSharedMemorySize, FQ_SMEM);
    fq_kernel<<<(kEdges + 63) / 64, 256, FQ_SMEM>>>(eattr, be, b2, W3, b3, out, kEdges);
}